// round 1
// baseline (speedup 1.0000x reference)
#include <cuda_runtime.h>
#include <math.h>

// Problem constants
#define B_    4
#define S_    2048
#define D_    1024
#define H_    16
#define DEPTH 64
#define MTOK  (B_ * S_)   // 8192 token rows

// Scratch (device globals; no allocation allowed in kernel_launch)
__device__ float g_q[B_ * H_ * S_ * DEPTH];     // [B,H,S,64]
__device__ float g_k[B_ * H_ * S_ * DEPTH];
__device__ float g_v[B_ * H_ * S_ * DEPTH];
__device__ float g_attn[MTOK * D_];             // [B,S,D] gathered heads

// ---------------------------------------------------------------------------
// 128x128x8 tiled SGEMM: C = (A[M,K] * W[K,N] + bias[N]) * alpha
// MODE 0: C row-major [M,N]
// MODE 1: C head-split [B,H,S,DEPTH]  (n -> (h, dd), m -> (b, s))
// M = 8192, N = K = 1024 (all tile-divisible, no bounds checks)
// ---------------------------------------------------------------------------
template <int MODE>
__global__ void __launch_bounds__(256)
sgemm_kernel(const float* __restrict__ A,
             const float* __restrict__ W,
             const float* __restrict__ bias,
             float* __restrict__ C,
             float alpha)
{
    const int K = D_;
    const int N = D_;

    __shared__ float As[8][128];   // transposed A tile: As[k][m]
    __shared__ float Bs[8][128];   // Bs[k][n]

    const int tid = threadIdx.x;
    const int ty  = tid >> 4;      // 0..15
    const int tx  = tid & 15;      // 0..15
    const int m0  = blockIdx.y * 128;
    const int n0  = blockIdx.x * 128;

    float acc[8][8];
    #pragma unroll
    for (int i = 0; i < 8; i++)
        #pragma unroll
        for (int j = 0; j < 8; j++)
            acc[i][j] = 0.0f;

    const int a_row = tid >> 1;          // 0..127
    const int a_k   = (tid & 1) * 4;     // 0 or 4
    const int b_k   = tid >> 5;          // 0..7
    const int b_n   = (tid & 31) * 4;    // 0..124

    for (int kb = 0; kb < K; kb += 8) {
        // Load A tile (128 rows x 8 k), transpose into As
        float4 av = *reinterpret_cast<const float4*>(&A[(size_t)(m0 + a_row) * K + kb + a_k]);
        As[a_k + 0][a_row] = av.x;
        As[a_k + 1][a_row] = av.y;
        As[a_k + 2][a_row] = av.z;
        As[a_k + 3][a_row] = av.w;
        // Load B tile (8 k x 128 n)
        float4 bv = *reinterpret_cast<const float4*>(&W[(size_t)(kb + b_k) * N + n0 + b_n]);
        *reinterpret_cast<float4*>(&Bs[b_k][b_n]) = bv;
        __syncthreads();

        #pragma unroll
        for (int k = 0; k < 8; k++) {
            float a[8], b[8];
            float4 a0 = *reinterpret_cast<const float4*>(&As[k][ty * 8]);
            float4 a1 = *reinterpret_cast<const float4*>(&As[k][ty * 8 + 4]);
            float4 b0 = *reinterpret_cast<const float4*>(&Bs[k][tx * 8]);
            float4 b1 = *reinterpret_cast<const float4*>(&Bs[k][tx * 8 + 4]);
            a[0]=a0.x; a[1]=a0.y; a[2]=a0.z; a[3]=a0.w;
            a[4]=a1.x; a[5]=a1.y; a[6]=a1.z; a[7]=a1.w;
            b[0]=b0.x; b[1]=b0.y; b[2]=b0.z; b[3]=b0.w;
            b[4]=b1.x; b[5]=b1.y; b[6]=b1.z; b[7]=b1.w;
            #pragma unroll
            for (int i = 0; i < 8; i++)
                #pragma unroll
                for (int j = 0; j < 8; j++)
                    acc[i][j] = fmaf(a[i], b[j], acc[i][j]);
        }
        __syncthreads();
    }

    // Epilogue
    #pragma unroll
    for (int i = 0; i < 8; i++) {
        const int m = m0 + ty * 8 + i;
        #pragma unroll
        for (int j = 0; j < 8; j++) {
            const int n = n0 + tx * 8 + j;
            const float v = (acc[i][j] + bias[n]) * alpha;
            if (MODE == 0) {
                C[(size_t)m * N + n] = v;
            } else {
                const int b  = m >> 11;        // m / 2048
                const int s  = m & 2047;
                const int h  = n >> 6;         // n / 64
                const int dd = n & 63;
                C[(((size_t)(b * H_ + h)) * S_ + s) * DEPTH + dd] = v;
            }
        }
    }
}

// ---------------------------------------------------------------------------
// Causal flash attention, fp32.
// Grid: (S/64, B*H). Block: 256 threads.
// Q pre-scaled by 1/sqrt(depth) at projection time.
// Tiles: BQ=BK=64, smem stride 65 (bank-conflict padding).
// O accumulators in registers (each thread owns a 4x4 microtile).
// ---------------------------------------------------------------------------
#define LDPAD 65
#define ATTN_SMEM_FLOATS (4 * 64 * LDPAD + 3 * 64)
#define ATTN_SMEM_BYTES  (ATTN_SMEM_FLOATS * 4)

__global__ void __launch_bounds__(256)
attn_kernel(float* __restrict__ out)
{
    extern __shared__ float sm[];
    float* Qs = sm;                      // [64][65]
    float* Ks = Qs + 64 * LDPAD;
    float* Vs = Ks + 64 * LDPAD;
    float* Ss = Vs + 64 * LDPAD;
    float* row_max   = Ss + 64 * LDPAD;  // [64]
    float* row_sum   = row_max + 64;
    float* row_alpha = row_sum + 64;

    const int tid = threadIdx.x;
    const int bh  = blockIdx.y;          // b*H + h
    const int qt  = blockIdx.x;          // q tile index
    const int q0  = qt * 64;

    const int ty = tid >> 4;             // 0..15
    const int tx = tid & 15;             // 0..15
    const int i0 = ty * 4;               // q-row base of microtile
    const int c0 = tx * 4;               // k-col (score) / d-col (output) base

    const float* Qg = g_q + ((size_t)bh * S_ + q0) * DEPTH;

    // Load Q tile (64x64) — 4 passes of float4 per thread
    {
        const int r = tid >> 4;
        const int c = (tid & 15) * 4;
        #pragma unroll
        for (int p = 0; p < 4; p++) {
            const int row = r + p * 16;
            float4 v = *reinterpret_cast<const float4*>(&Qg[row * DEPTH + c]);
            Qs[row * LDPAD + c + 0] = v.x;
            Qs[row * LDPAD + c + 1] = v.y;
            Qs[row * LDPAD + c + 2] = v.z;
            Qs[row * LDPAD + c + 3] = v.w;
        }
    }
    if (tid < 64) {
        row_max[tid] = -1e30f;
        row_sum[tid] = 0.0f;
    }

    float o[4][4];
    #pragma unroll
    for (int i = 0; i < 4; i++)
        #pragma unroll
        for (int j = 0; j < 4; j++)
            o[i][j] = 0.0f;

    for (int kt = 0; kt <= qt; kt++) {
        __syncthreads();   // previous iteration's reads of Ks/Vs/Ss complete

        const float* Kg = g_k + ((size_t)bh * S_ + kt * 64) * DEPTH;
        const float* Vg = g_v + ((size_t)bh * S_ + kt * 64) * DEPTH;
        {
            const int r = tid >> 4;
            const int c = (tid & 15) * 4;
            #pragma unroll
            for (int p = 0; p < 4; p++) {
                const int row = r + p * 16;
                float4 kv = *reinterpret_cast<const float4*>(&Kg[row * DEPTH + c]);
                Ks[row * LDPAD + c + 0] = kv.x;
                Ks[row * LDPAD + c + 1] = kv.y;
                Ks[row * LDPAD + c + 2] = kv.z;
                Ks[row * LDPAD + c + 3] = kv.w;
                float4 vv = *reinterpret_cast<const float4*>(&Vg[row * DEPTH + c]);
                Vs[row * LDPAD + c + 0] = vv.x;
                Vs[row * LDPAD + c + 1] = vv.y;
                Vs[row * LDPAD + c + 2] = vv.z;
                Vs[row * LDPAD + c + 3] = vv.w;
            }
        }
        __syncthreads();

        // Scores: S[i][j] = sum_d Q[i][d]*K[j][d]   (Q pre-scaled)
        float acc[4][4];
        #pragma unroll
        for (int i = 0; i < 4; i++)
            #pragma unroll
            for (int j = 0; j < 4; j++)
                acc[i][j] = 0.0f;

        #pragma unroll 4
        for (int d = 0; d < DEPTH; d++) {
            float qv[4], kv[4];
            #pragma unroll
            for (int ii = 0; ii < 4; ii++) qv[ii] = Qs[(i0 + ii) * LDPAD + d];
            #pragma unroll
            for (int jj = 0; jj < 4; jj++) kv[jj] = Ks[(c0 + jj) * LDPAD + d];
            #pragma unroll
            for (int ii = 0; ii < 4; ii++)
                #pragma unroll
                for (int jj = 0; jj < 4; jj++)
                    acc[ii][jj] = fmaf(qv[ii], kv[jj], acc[ii][jj]);
        }

        const bool diag = (kt == qt);
        #pragma unroll
        for (int ii = 0; ii < 4; ii++)
            #pragma unroll
            for (int jj = 0; jj < 4; jj++) {
                float s = acc[ii][jj];
                if (diag && (c0 + jj) > (i0 + ii)) s = -1e30f;  // causal mask
                Ss[(i0 + ii) * LDPAD + (c0 + jj)] = s;
            }
        __syncthreads();

        // Online softmax per row (64 rows, one thread each)
        if (tid < 64) {
            float* srow = &Ss[tid * LDPAD];
            float m = -1e30f;
            #pragma unroll 8
            for (int j = 0; j < 64; j++) m = fmaxf(m, srow[j]);
            const float old_m = row_max[tid];
            const float nm = fmaxf(old_m, m);
            const float corr = __expf(old_m - nm);
            float sum = 0.0f;
            #pragma unroll 8
            for (int j = 0; j < 64; j++) {
                const float p = __expf(srow[j] - nm);
                srow[j] = p;
                sum += p;
            }
            row_sum[tid]   = row_sum[tid] * corr + sum;
            row_max[tid]   = nm;
            row_alpha[tid] = corr;
        }
        __syncthreads();

        // O update: O = O*alpha_row + P @ V
        float al[4];
        #pragma unroll
        for (int ii = 0; ii < 4; ii++) al[ii] = row_alpha[i0 + ii];

        float pacc[4][4];
        #pragma unroll
        for (int i = 0; i < 4; i++)
            #pragma unroll
            for (int j = 0; j < 4; j++)
                pacc[i][j] = 0.0f;

        #pragma unroll 4
        for (int j = 0; j < 64; j++) {
            float pv[4], vv[4];
            #pragma unroll
            for (int ii = 0; ii < 4; ii++) pv[ii] = Ss[(i0 + ii) * LDPAD + j];
            #pragma unroll
            for (int dd = 0; dd < 4; dd++) vv[dd] = Vs[j * LDPAD + c0 + dd];
            #pragma unroll
            for (int ii = 0; ii < 4; ii++)
                #pragma unroll
                for (int dd = 0; dd < 4; dd++)
                    pacc[ii][dd] = fmaf(pv[ii], vv[dd], pacc[ii][dd]);
        }
        #pragma unroll
        for (int ii = 0; ii < 4; ii++)
            #pragma unroll
            for (int dd = 0; dd < 4; dd++)
                o[ii][dd] = o[ii][dd] * al[ii] + pacc[ii][dd];
    }

    // Normalize and write to [B,S,D] with head gather
    const int b = bh >> 4;
    const int h = bh & 15;
    #pragma unroll
    for (int ii = 0; ii < 4; ii++) {
        const float inv = 1.0f / row_sum[i0 + ii];
        const size_t base = ((size_t)b * S_ + (q0 + i0 + ii)) * D_ + h * DEPTH + c0;
        #pragma unroll
        for (int dd = 0; dd < 4; dd++)
            out[base + dd] = o[ii][dd] * inv;
    }
}

// ---------------------------------------------------------------------------
// Launch
// ---------------------------------------------------------------------------
extern "C" void kernel_launch(void* const* d_in, const int* in_sizes, int n_in,
                              void* d_out, int out_size)
{
    (void)in_sizes; (void)n_in; (void)out_size;
    const float* v_in = (const float*)d_in[0];
    const float* k_in = (const float*)d_in[1];
    const float* q_in = (const float*)d_in[2];
    // d_in[3] = mask (strict upper triangle) — implemented as exact causal skip
    const float* wq = (const float*)d_in[4];
    const float* bq = (const float*)d_in[5];
    const float* wk = (const float*)d_in[6];
    const float* bk = (const float*)d_in[7];
    const float* wv = (const float*)d_in[8];
    const float* bv = (const float*)d_in[9];
    const float* wo = (const float*)d_in[10];
    const float* bo = (const float*)d_in[11];
    float* out = (float*)d_out;

    float *gq, *gk, *gv, *gattn;
    cudaGetSymbolAddress((void**)&gq, g_q);
    cudaGetSymbolAddress((void**)&gk, g_k);
    cudaGetSymbolAddress((void**)&gv, g_v);
    cudaGetSymbolAddress((void**)&gattn, g_attn);

    static bool attr_set = false;
    if (!attr_set) {
        cudaFuncSetAttribute(attn_kernel,
                             cudaFuncAttributeMaxDynamicSharedMemorySize,
                             ATTN_SMEM_BYTES);
        attr_set = true;
    }

    const dim3 gemm_grid(D_ / 128, MTOK / 128);   // (8, 64)
    const dim3 gemm_block(256);
    const float qscale = 1.0f / sqrtf((float)DEPTH);   // 0.125

    // Projections (head-split output); Q pre-scaled by 1/sqrt(depth)
    sgemm_kernel<1><<<gemm_grid, gemm_block>>>(q_in, wq, bq, gq, qscale);
    sgemm_kernel<1><<<gemm_grid, gemm_block>>>(k_in, wk, bk, gk, 1.0f);
    sgemm_kernel<1><<<gemm_grid, gemm_block>>>(v_in, wv, bv, gv, 1.0f);

    // Causal flash attention -> [B,S,D]
    const dim3 attn_grid(S_ / 64, B_ * H_);       // (32, 64)
    attn_kernel<<<attn_grid, 256, ATTN_SMEM_BYTES>>>(gattn);

    // Output projection
    sgemm_kernel<0><<<gemm_grid, gemm_block>>>(gattn, wo, bo, out, 1.0f);
}

// round 3
// speedup vs baseline: 1.5629x; 1.5629x over previous
#include <cuda_runtime.h>
#include <cuda_bf16.h>
#include <math.h>
#include <stdint.h>

// Problem constants
#define B_    4
#define S_    2048
#define D_    1024
#define H_    16
#define DEPTH 64
#define MTOK  (B_ * S_)   // 8192 token rows

// ---------------------------------------------------------------------------
// Scratch (device globals; no allocation allowed)
// ---------------------------------------------------------------------------
__device__ float g_q[B_ * H_ * S_ * DEPTH];     // [B,H,S,64] fp32 (attn inputs)
__device__ float g_k[B_ * H_ * S_ * DEPTH];
__device__ float g_v[B_ * H_ * S_ * DEPTH];

// split-bf16 inputs (v,k,q order matches d_in)
__device__ __nv_bfloat16 g_in_hi[3][MTOK * D_];
__device__ __nv_bfloat16 g_in_lo[3][MTOK * D_];
// split-bf16 transposed weights [N,K] (wq,wk,wv,wo)
__device__ __nv_bfloat16 g_wt_hi[4][D_ * D_];
__device__ __nv_bfloat16 g_wt_lo[4][D_ * D_];
// attention output, split-bf16 [B,S,D]
__device__ __nv_bfloat16 g_attn_hi[MTOK * D_];
__device__ __nv_bfloat16 g_attn_lo[MTOK * D_];

// ---------------------------------------------------------------------------
// PTX helpers (sm_103 base target: mma.sync / ldmatrix / cp.async only)
// ---------------------------------------------------------------------------
__device__ __forceinline__ uint32_t smem_u32(const void* p) {
    uint32_t a;
    asm("{ .reg .u64 t; cvta.to.shared.u64 t, %1; cvt.u32.u64 %0, t; }"
        : "=r"(a) : "l"(p));
    return a;
}

#define CP_ASYNC16(dst_u32, src_ptr) \
    asm volatile("cp.async.cg.shared.global [%0], [%1], 16;" \
                 :: "r"(dst_u32), "l"(src_ptr) : "memory")
#define CP_COMMIT() asm volatile("cp.async.commit_group;" ::: "memory")
#define CP_WAIT(n)  asm volatile("cp.async.wait_group %0;" :: "n"(n) : "memory")

#define LDSM_X4(r0, r1, r2, r3, addr) \
    asm volatile("ldmatrix.sync.aligned.m8n8.x4.shared.b16 {%0,%1,%2,%3}, [%4];" \
                 : "=r"(r0), "=r"(r1), "=r"(r2), "=r"(r3) : "r"(addr))

#define MMA_BF16(d, a, b) \
    asm volatile("mma.sync.aligned.m16n8k16.row.col.f32.bf16.bf16.f32 " \
                 "{%0,%1,%2,%3}, {%4,%5,%6,%7}, {%8,%9}, {%0,%1,%2,%3};" \
                 : "+f"((d)[0]), "+f"((d)[1]), "+f"((d)[2]), "+f"((d)[3]) \
                 : "r"((a)[0]), "r"((a)[1]), "r"((a)[2]), "r"((a)[3]), \
                   "r"((b)[0]), "r"((b)[1]))

__device__ __forceinline__ void split_bf16(float x, __nv_bfloat16& h, __nv_bfloat16& l) {
    h = __float2bfloat16(x);
    l = __float2bfloat16(x - __bfloat162float(h));
}

// ---------------------------------------------------------------------------
// Conversion kernels
// ---------------------------------------------------------------------------
__global__ void __launch_bounds__(256)
convert_split_kernel(const float* __restrict__ in,
                     __nv_bfloat16* __restrict__ hi,
                     __nv_bfloat16* __restrict__ lo, int n4)
{
    int i = blockIdx.x * blockDim.x + threadIdx.x;
    if (i >= n4) return;
    float4 v = reinterpret_cast<const float4*>(in)[i];
    __nv_bfloat16 h0, h1, h2, h3, l0, l1, l2, l3;
    split_bf16(v.x, h0, l0); split_bf16(v.y, h1, l1);
    split_bf16(v.z, h2, l2); split_bf16(v.w, h3, l3);
    __nv_bfloat162* hp = reinterpret_cast<__nv_bfloat162*>(hi);
    __nv_bfloat162* lp = reinterpret_cast<__nv_bfloat162*>(lo);
    __nv_bfloat162 a; a.x = h0; a.y = h1;
    __nv_bfloat162 b; b.x = h2; b.y = h3;
    __nv_bfloat162 c; c.x = l0; c.y = l1;
    __nv_bfloat162 d; d.x = l2; d.y = l3;
    hp[2 * i] = a; hp[2 * i + 1] = b;
    lp[2 * i] = c; lp[2 * i + 1] = d;
}

// W[K,N] fp32 -> Wt_hi/lo [N,K] bf16 (transpose + split)
__global__ void __launch_bounds__(256)
transpose_split_kernel(const float* __restrict__ W,
                       __nv_bfloat16* __restrict__ Th,
                       __nv_bfloat16* __restrict__ Tl)
{
    __shared__ float t[32][33];
    const int tx = threadIdx.x, ty = threadIdx.y;   // (32, 8)
    const int kx = blockIdx.y * 32;                 // K tile
    const int nx = blockIdx.x * 32;                 // N tile
    #pragma unroll
    for (int r = 0; r < 32; r += 8)
        t[ty + r][tx] = W[(size_t)(kx + ty + r) * D_ + nx + tx];
    __syncthreads();
    #pragma unroll
    for (int r = 0; r < 32; r += 8) {
        const int n = nx + ty + r;
        const int k = kx + tx;
        __nv_bfloat16 h, l;
        split_bf16(t[tx][ty + r], h, l);
        Th[(size_t)n * D_ + k] = h;
        Tl[(size_t)n * D_ + k] = l;
    }
}

// ---------------------------------------------------------------------------
// HMMA bf16x3 GEMM via mma.sync:
//   C[M,N] = (sum_k A(m,k)*W(k,n) + bias[n]) * alpha
//   A: Ah/Al [M,K] bf16 row-major;  B: Bh/Bl [N,K] bf16 row-major (W^T)
//   M=8192, N=K=1024. CTA tile 128x128, K-block 32, 8 warps (4x2).
//   Each warp: 32x64 = 2 x 8 m16n8 fragments. bf16x3: hh + hl + lh.
// MODE 0: C row-major [M,N]; MODE 1: C head-split [B,H,S,DEPTH]
// ---------------------------------------------------------------------------
#define LDT       40          // smem row stride in bf16 (80 bytes; conflict-free)
#define TILE_B    (128 * LDT * 2)          // 10240 bytes per tile
#define STAGE_B   (4 * TILE_B)             // Ah, Al, Bh, Bl = 40960
#define GEMM_SMEM (2 * STAGE_B)            // 81920

template <int MODE>
__global__ void __launch_bounds__(256)
mma_gemm(const __nv_bfloat16* __restrict__ Ah, const __nv_bfloat16* __restrict__ Al,
         const __nv_bfloat16* __restrict__ Bh, const __nv_bfloat16* __restrict__ Bl,
         const float* __restrict__ bias, float* __restrict__ C, float alpha)
{
    extern __shared__ char smem[];
    const uint32_t sb = smem_u32(smem);

    const int tid  = threadIdx.x;
    const int wid  = tid >> 5;
    const int lane = tid & 31;
    const int wm   = wid & 3;          // warp row  (0..3) -> 32 rows each
    const int wn   = wid >> 2;         // warp col  (0..1) -> 64 cols each
    const int m0   = blockIdx.y * 128;
    const int n0   = blockIdx.x * 128;

    const __nv_bfloat16* srcs[4] = {Ah, Al, Bh, Bl};
    const int rowbase[4] = {m0, m0, n0, n0};

    // ---- loader lambda: stage kb (K-block index) into buffer buf ----
    auto load_stage = [&](int kb, int buf) {
        const uint32_t st = sb + buf * STAGE_B;
        #pragma unroll
        for (int t = 0; t < 4; t++) {
            const __nv_bfloat16* s = srcs[t];
            const int rb = rowbase[t];
            #pragma unroll
            for (int r = 0; r < 2; r++) {
                const int idx  = r * 256 + tid;
                const int row  = idx >> 2;
                const int ch   = idx & 3;
                const __nv_bfloat16* src = s + (size_t)(rb + row) * D_ + kb * 32 + ch * 8;
                const uint32_t dst = st + t * TILE_B + row * (LDT * 2) + ch * 16;
                CP_ASYNC16(dst, src);
            }
        }
        CP_COMMIT();
    };

    float acc[2][8][4];
    #pragma unroll
    for (int i = 0; i < 2; i++)
        #pragma unroll
        for (int j = 0; j < 8; j++)
            #pragma unroll
            for (int v = 0; v < 4; v++)
                acc[i][j][v] = 0.0f;

    load_stage(0, 0);
    load_stage(1, 1);

    // ldmatrix lane addressing (within a tile):
    // A (m16k16 frag): lanes 0-15 -> rows 0..15 col ks; 16-31 -> rows 0..15 col ks+8
    const int a_r = lane & 15;
    const int a_c = (lane >> 4) << 3;
    // B (two n8k16 frags): row = gp*16 + (lane&7) + ((lane>>4)<<3); col = ks + ((lane>>3)&1)*8
    const int b_r = (lane & 7) + ((lane >> 4) << 3);
    const int b_c = ((lane >> 3) & 1) << 3;

    const int NITER = D_ / 32;   // 32
    for (int kb = 0; kb < NITER; kb++) {
        const int buf = kb & 1;
        if (kb == NITER - 1) { CP_WAIT(0); } else { CP_WAIT(1); }
        __syncthreads();

        const uint32_t st  = sb + buf * STAGE_B;
        const uint32_t tAh = st;
        const uint32_t tAl = st + TILE_B;
        const uint32_t tBh = st + 2 * TILE_B;
        const uint32_t tBl = st + 3 * TILE_B;

        #pragma unroll
        for (int ks = 0; ks < 32; ks += 16) {
            uint32_t ah[2][4], al_[2][4];
            #pragma unroll
            for (int mf = 0; mf < 2; mf++) {
                const int row = wm * 32 + mf * 16 + a_r;
                const uint32_t off = row * (LDT * 2) + (ks + a_c) * 2;
                LDSM_X4(ah[mf][0], ah[mf][1], ah[mf][2], ah[mf][3], tAh + off);
                LDSM_X4(al_[mf][0], al_[mf][1], al_[mf][2], al_[mf][3], tAl + off);
            }
            uint32_t bh[8][2], bl[8][2];
            #pragma unroll
            for (int gp = 0; gp < 4; gp++) {
                const int row = wn * 64 + gp * 16 + b_r;
                const uint32_t off = row * (LDT * 2) + (ks + b_c) * 2;
                LDSM_X4(bh[2 * gp][0], bh[2 * gp][1], bh[2 * gp + 1][0], bh[2 * gp + 1][1],
                        tBh + off);
                LDSM_X4(bl[2 * gp][0], bl[2 * gp][1], bl[2 * gp + 1][0], bl[2 * gp + 1][1],
                        tBl + off);
            }
            #pragma unroll
            for (int mf = 0; mf < 2; mf++)
                #pragma unroll
                for (int nf = 0; nf < 8; nf++) {
                    MMA_BF16(acc[mf][nf], ah[mf], bh[nf]);
                    MMA_BF16(acc[mf][nf], ah[mf], bl[nf]);
                    MMA_BF16(acc[mf][nf], al_[mf], bh[nf]);
                }
        }
        __syncthreads();
        if (kb + 2 < NITER) load_stage(kb + 2, buf);
    }

    // Epilogue: c0,c1 -> (row, col..col+1); c2,c3 -> (row+8, col..col+1)
    const int er = lane >> 2;
    const int ec = (lane & 3) * 2;
    #pragma unroll
    for (int mf = 0; mf < 2; mf++) {
        #pragma unroll
        for (int nf = 0; nf < 8; nf++) {
            const int n  = n0 + wn * 64 + nf * 8 + ec;
            const float b0 = bias[n], b1 = bias[n + 1];
            #pragma unroll
            for (int half = 0; half < 2; half++) {
                const int m = m0 + wm * 32 + mf * 16 + er + half * 8;
                float2 v;
                v.x = (acc[mf][nf][half * 2 + 0] + b0) * alpha;
                v.y = (acc[mf][nf][half * 2 + 1] + b1) * alpha;
                if (MODE == 0) {
                    *reinterpret_cast<float2*>(&C[(size_t)m * D_ + n]) = v;
                } else {
                    const int b  = m >> 11;
                    const int s  = m & 2047;
                    const int h  = n >> 6;
                    const int dd = n & 63;
                    *reinterpret_cast<float2*>(
                        &C[(((size_t)(b * H_ + h)) * S_ + s) * DEPTH + dd]) = v;
                }
            }
        }
    }
}

// ---------------------------------------------------------------------------
// Causal flash attention, fp32 (unchanged math; writes split-bf16 output)
// ---------------------------------------------------------------------------
#define LDPAD 65
#define ATTN_SMEM_FLOATS (4 * 64 * LDPAD + 3 * 64)
#define ATTN_SMEM_BYTES  (ATTN_SMEM_FLOATS * 4)

__global__ void __launch_bounds__(256)
attn_kernel(__nv_bfloat16* __restrict__ out_hi, __nv_bfloat16* __restrict__ out_lo)
{
    extern __shared__ float sm[];
    float* Qs = sm;
    float* Ks = Qs + 64 * LDPAD;
    float* Vs = Ks + 64 * LDPAD;
    float* Ss = Vs + 64 * LDPAD;
    float* row_max   = Ss + 64 * LDPAD;
    float* row_sum   = row_max + 64;
    float* row_alpha = row_sum + 64;

    const int tid = threadIdx.x;
    const int bh  = blockIdx.y;
    const int qt  = blockIdx.x;
    const int q0  = qt * 64;

    const int ty = tid >> 4;
    const int tx = tid & 15;
    const int i0 = ty * 4;
    const int c0 = tx * 4;

    const float* Qg = g_q + ((size_t)bh * S_ + q0) * DEPTH;
    {
        const int r = tid >> 4;
        const int c = (tid & 15) * 4;
        #pragma unroll
        for (int p = 0; p < 4; p++) {
            const int row = r + p * 16;
            float4 v = *reinterpret_cast<const float4*>(&Qg[row * DEPTH + c]);
            Qs[row * LDPAD + c + 0] = v.x;
            Qs[row * LDPAD + c + 1] = v.y;
            Qs[row * LDPAD + c + 2] = v.z;
            Qs[row * LDPAD + c + 3] = v.w;
        }
    }
    if (tid < 64) { row_max[tid] = -1e30f; row_sum[tid] = 0.0f; }

    float o[4][4];
    #pragma unroll
    for (int i = 0; i < 4; i++)
        #pragma unroll
        for (int j = 0; j < 4; j++) o[i][j] = 0.0f;

    for (int kt = 0; kt <= qt; kt++) {
        __syncthreads();
        const float* Kg = g_k + ((size_t)bh * S_ + kt * 64) * DEPTH;
        const float* Vg = g_v + ((size_t)bh * S_ + kt * 64) * DEPTH;
        {
            const int r = tid >> 4;
            const int c = (tid & 15) * 4;
            #pragma unroll
            for (int p = 0; p < 4; p++) {
                const int row = r + p * 16;
                float4 kv = *reinterpret_cast<const float4*>(&Kg[row * DEPTH + c]);
                Ks[row * LDPAD + c + 0] = kv.x;
                Ks[row * LDPAD + c + 1] = kv.y;
                Ks[row * LDPAD + c + 2] = kv.z;
                Ks[row * LDPAD + c + 3] = kv.w;
                float4 vv = *reinterpret_cast<const float4*>(&Vg[row * DEPTH + c]);
                Vs[row * LDPAD + c + 0] = vv.x;
                Vs[row * LDPAD + c + 1] = vv.y;
                Vs[row * LDPAD + c + 2] = vv.z;
                Vs[row * LDPAD + c + 3] = vv.w;
            }
        }
        __syncthreads();

        float acc[4][4];
        #pragma unroll
        for (int i = 0; i < 4; i++)
            #pragma unroll
            for (int j = 0; j < 4; j++) acc[i][j] = 0.0f;

        #pragma unroll 4
        for (int d = 0; d < DEPTH; d++) {
            float qv[4], kv[4];
            #pragma unroll
            for (int ii = 0; ii < 4; ii++) qv[ii] = Qs[(i0 + ii) * LDPAD + d];
            #pragma unroll
            for (int jj = 0; jj < 4; jj++) kv[jj] = Ks[(c0 + jj) * LDPAD + d];
            #pragma unroll
            for (int ii = 0; ii < 4; ii++)
                #pragma unroll
                for (int jj = 0; jj < 4; jj++)
                    acc[ii][jj] = fmaf(qv[ii], kv[jj], acc[ii][jj]);
        }

        const bool diag = (kt == qt);
        #pragma unroll
        for (int ii = 0; ii < 4; ii++)
            #pragma unroll
            for (int jj = 0; jj < 4; jj++) {
                float s = acc[ii][jj];
                if (diag && (c0 + jj) > (i0 + ii)) s = -1e30f;
                Ss[(i0 + ii) * LDPAD + (c0 + jj)] = s;
            }
        __syncthreads();

        if (tid < 64) {
            float* srow = &Ss[tid * LDPAD];
            float m = -1e30f;
            #pragma unroll 8
            for (int j = 0; j < 64; j++) m = fmaxf(m, srow[j]);
            const float old_m = row_max[tid];
            const float nm = fmaxf(old_m, m);
            const float corr = __expf(old_m - nm);
            float sum = 0.0f;
            #pragma unroll 8
            for (int j = 0; j < 64; j++) {
                const float p = __expf(srow[j] - nm);
                srow[j] = p;
                sum += p;
            }
            row_sum[tid]   = row_sum[tid] * corr + sum;
            row_max[tid]   = nm;
            row_alpha[tid] = corr;
        }
        __syncthreads();

        float al[4];
        #pragma unroll
        for (int ii = 0; ii < 4; ii++) al[ii] = row_alpha[i0 + ii];

        float pacc[4][4];
        #pragma unroll
        for (int i = 0; i < 4; i++)
            #pragma unroll
            for (int j = 0; j < 4; j++) pacc[i][j] = 0.0f;

        #pragma unroll 4
        for (int j = 0; j < 64; j++) {
            float pv[4], vv[4];
            #pragma unroll
            for (int ii = 0; ii < 4; ii++) pv[ii] = Ss[(i0 + ii) * LDPAD + j];
            #pragma unroll
            for (int dd = 0; dd < 4; dd++) vv[dd] = Vs[j * LDPAD + c0 + dd];
            #pragma unroll
            for (int ii = 0; ii < 4; ii++)
                #pragma unroll
                for (int dd = 0; dd < 4; dd++)
                    pacc[ii][dd] = fmaf(pv[ii], vv[dd], pacc[ii][dd]);
        }
        #pragma unroll
        for (int ii = 0; ii < 4; ii++)
            #pragma unroll
            for (int dd = 0; dd < 4; dd++)
                o[ii][dd] = o[ii][dd] * al[ii] + pacc[ii][dd];
    }

    const int b = bh >> 4;
    const int h = bh & 15;
    #pragma unroll
    for (int ii = 0; ii < 4; ii++) {
        const float inv = 1.0f / row_sum[i0 + ii];
        const size_t base = ((size_t)b * S_ + (q0 + i0 + ii)) * D_ + h * DEPTH + c0;
        #pragma unroll
        for (int dd = 0; dd < 4; dd++) {
            const float val = o[ii][dd] * inv;
            __nv_bfloat16 hv, lv;
            split_bf16(val, hv, lv);
            out_hi[base + dd] = hv;
            out_lo[base + dd] = lv;
        }
    }
}

// ---------------------------------------------------------------------------
// Launch
// ---------------------------------------------------------------------------
extern "C" void kernel_launch(void* const* d_in, const int* in_sizes, int n_in,
                              void* d_out, int out_size)
{
    (void)in_sizes; (void)n_in; (void)out_size;
    const float* v_in = (const float*)d_in[0];
    const float* k_in = (const float*)d_in[1];
    const float* q_in = (const float*)d_in[2];
    const float* wq = (const float*)d_in[4];
    const float* bq = (const float*)d_in[5];
    const float* wk = (const float*)d_in[6];
    const float* bk = (const float*)d_in[7];
    const float* wv = (const float*)d_in[8];
    const float* bv = (const float*)d_in[9];
    const float* wo = (const float*)d_in[10];
    const float* bo = (const float*)d_in[11];
    float* out = (float*)d_out;

    float *gq, *gk, *gv;
    __nv_bfloat16 *ih, *il, *wh, *wl, *ah, *al;
    cudaGetSymbolAddress((void**)&gq, g_q);
    cudaGetSymbolAddress((void**)&gk, g_k);
    cudaGetSymbolAddress((void**)&gv, g_v);
    cudaGetSymbolAddress((void**)&ih, g_in_hi);
    cudaGetSymbolAddress((void**)&il, g_in_lo);
    cudaGetSymbolAddress((void**)&wh, g_wt_hi);
    cudaGetSymbolAddress((void**)&wl, g_wt_lo);
    cudaGetSymbolAddress((void**)&ah, g_attn_hi);
    cudaGetSymbolAddress((void**)&al, g_attn_lo);

    static bool attr_set = false;
    if (!attr_set) {
        cudaFuncSetAttribute(attn_kernel,
                             cudaFuncAttributeMaxDynamicSharedMemorySize, ATTN_SMEM_BYTES);
        cudaFuncSetAttribute(mma_gemm<0>,
                             cudaFuncAttributeMaxDynamicSharedMemorySize, GEMM_SMEM);
        cudaFuncSetAttribute(mma_gemm<1>,
                             cudaFuncAttributeMaxDynamicSharedMemorySize, GEMM_SMEM);
        attr_set = true;
    }

    const size_t ND = (size_t)MTOK * D_;
    const size_t WD = (size_t)D_ * D_;

    // 1) Split inputs (v,k,q) into bf16 hi/lo
    const int n4 = (int)(ND / 4);
    const int cgrid = (n4 + 255) / 256;
    convert_split_kernel<<<cgrid, 256>>>(v_in, ih + 0 * ND, il + 0 * ND, n4);
    convert_split_kernel<<<cgrid, 256>>>(k_in, ih + 1 * ND, il + 1 * ND, n4);
    convert_split_kernel<<<cgrid, 256>>>(q_in, ih + 2 * ND, il + 2 * ND, n4);

    // 2) Transpose + split weights (wq, wk, wv, wo)
    const dim3 tgrid(32, 32), tblock(32, 8);
    transpose_split_kernel<<<tgrid, tblock>>>(wq, wh + 0 * WD, wl + 0 * WD);
    transpose_split_kernel<<<tgrid, tblock>>>(wk, wh + 1 * WD, wl + 1 * WD);
    transpose_split_kernel<<<tgrid, tblock>>>(wv, wh + 2 * WD, wl + 2 * WD);
    transpose_split_kernel<<<tgrid, tblock>>>(wo, wh + 3 * WD, wl + 3 * WD);

    // 3) Projections via HMMA (head-split outputs); Q pre-scaled by 1/8
    const dim3 ggrid(D_ / 128, MTOK / 128);   // (8, 64)
    const float qscale = 0.125f;
    mma_gemm<1><<<ggrid, 256, GEMM_SMEM>>>(ih + 2 * ND, il + 2 * ND,
                                           wh + 0 * WD, wl + 0 * WD, bq, gq, qscale);
    mma_gemm<1><<<ggrid, 256, GEMM_SMEM>>>(ih + 1 * ND, il + 1 * ND,
                                           wh + 1 * WD, wl + 1 * WD, bk, gk, 1.0f);
    mma_gemm<1><<<ggrid, 256, GEMM_SMEM>>>(ih + 0 * ND, il + 0 * ND,
                                           wh + 2 * WD, wl + 2 * WD, bv, gv, 1.0f);

    // 4) Causal flash attention -> split-bf16 [B,S,D]
    const dim3 attn_grid(S_ / 64, B_ * H_);
    attn_kernel<<<attn_grid, 256, ATTN_SMEM_BYTES>>>(ah, al);

    // 5) Output projection (fp32 out)
    mma_gemm<0><<<ggrid, 256, GEMM_SMEM>>>(ah, al, wh + 3 * WD, wl + 3 * WD, bo, out, 1.0f);
}

// round 4
// speedup vs baseline: 3.0086x; 1.9250x over previous
#include <cuda_runtime.h>
#include <cuda_bf16.h>
#include <math.h>
#include <stdint.h>

// Problem constants
#define B_    4
#define S_    2048
#define D_    1024
#define H_    16
#define DEPTH 64
#define MTOK  (B_ * S_)   // 8192 token rows

// ---------------------------------------------------------------------------
// Scratch (device globals; no allocation allowed)
// ---------------------------------------------------------------------------
// split-bf16 inputs (v,k,q order matches d_in)
__device__ __nv_bfloat16 g_in_hi[3][MTOK * D_];
__device__ __nv_bfloat16 g_in_lo[3][MTOK * D_];
// split-bf16 transposed weights [N,K] (wq,wk,wv,wo)
__device__ __nv_bfloat16 g_wt_hi[4][D_ * D_];
__device__ __nv_bfloat16 g_wt_lo[4][D_ * D_];
// projected q/k/v, split bf16, head-split [B,H,S,64]
__device__ __nv_bfloat16 g_qh[MTOK * D_];
__device__ __nv_bfloat16 g_ql[MTOK * D_];
__device__ __nv_bfloat16 g_kh[MTOK * D_];
__device__ __nv_bfloat16 g_kl[MTOK * D_];
__device__ __nv_bfloat16 g_vh[MTOK * D_];
__device__ __nv_bfloat16 g_vl[MTOK * D_];
// attention output, split-bf16 [B,S,D]
__device__ __nv_bfloat16 g_attn_hi[MTOK * D_];
__device__ __nv_bfloat16 g_attn_lo[MTOK * D_];

// ---------------------------------------------------------------------------
// PTX helpers (sm_103 base target: mma.sync / ldmatrix / cp.async only)
// ---------------------------------------------------------------------------
__device__ __forceinline__ uint32_t smem_u32(const void* p) {
    uint32_t a;
    asm("{ .reg .u64 t; cvta.to.shared.u64 t, %1; cvt.u32.u64 %0, t; }"
        : "=r"(a) : "l"(p));
    return a;
}

#define CP_ASYNC16(dst_u32, src_ptr) \
    asm volatile("cp.async.cg.shared.global [%0], [%1], 16;" \
                 :: "r"(dst_u32), "l"(src_ptr) : "memory")
#define CP_COMMIT() asm volatile("cp.async.commit_group;" ::: "memory")
#define CP_WAIT(n)  asm volatile("cp.async.wait_group %0;" :: "n"(n) : "memory")

#define LDSM_X4(r0, r1, r2, r3, addr) \
    asm volatile("ldmatrix.sync.aligned.m8n8.x4.shared.b16 {%0,%1,%2,%3}, [%4];" \
                 : "=r"(r0), "=r"(r1), "=r"(r2), "=r"(r3) : "r"(addr))

#define LDSM_X4_T(r0, r1, r2, r3, addr) \
    asm volatile("ldmatrix.sync.aligned.m8n8.x4.trans.shared.b16 {%0,%1,%2,%3}, [%4];" \
                 : "=r"(r0), "=r"(r1), "=r"(r2), "=r"(r3) : "r"(addr))

#define MMA_BF16(d, a, b) \
    asm volatile("mma.sync.aligned.m16n8k16.row.col.f32.bf16.bf16.f32 " \
                 "{%0,%1,%2,%3}, {%4,%5,%6,%7}, {%8,%9}, {%0,%1,%2,%3};" \
                 : "+f"((d)[0]), "+f"((d)[1]), "+f"((d)[2]), "+f"((d)[3]) \
                 : "r"((a)[0]), "r"((a)[1]), "r"((a)[2]), "r"((a)[3]), \
                   "r"((b)[0]), "r"((b)[1]))

__device__ __forceinline__ void split_bf16(float x, __nv_bfloat16& h, __nv_bfloat16& l) {
    h = __float2bfloat16(x);
    l = __float2bfloat16(x - __bfloat162float(h));
}

// pack two floats into hi-pair and lo-pair bf16x2 registers
__device__ __forceinline__ void split_pack2(float x, float y, uint32_t& hi, uint32_t& lo) {
    __nv_bfloat16 xh, xl, yh, yl;
    split_bf16(x, xh, xl);
    split_bf16(y, yh, yl);
    __nv_bfloat162 h2; h2.x = xh; h2.y = yh;
    __nv_bfloat162 l2; l2.x = xl; l2.y = yl;
    hi = *reinterpret_cast<uint32_t*>(&h2);
    lo = *reinterpret_cast<uint32_t*>(&l2);
}

// ---------------------------------------------------------------------------
// Conversion kernels
// ---------------------------------------------------------------------------
__global__ void __launch_bounds__(256)
convert_split_kernel(const float* __restrict__ in,
                     __nv_bfloat16* __restrict__ hi,
                     __nv_bfloat16* __restrict__ lo, int n4)
{
    int i = blockIdx.x * blockDim.x + threadIdx.x;
    if (i >= n4) return;
    float4 v = reinterpret_cast<const float4*>(in)[i];
    uint32_t h0, l0, h1, l1;
    split_pack2(v.x, v.y, h0, l0);
    split_pack2(v.z, v.w, h1, l1);
    uint32_t* hp = reinterpret_cast<uint32_t*>(hi);
    uint32_t* lp = reinterpret_cast<uint32_t*>(lo);
    hp[2 * i] = h0; hp[2 * i + 1] = h1;
    lp[2 * i] = l0; lp[2 * i + 1] = l1;
}

// W[K,N] fp32 -> Wt_hi/lo [N,K] bf16 (transpose + split)
__global__ void __launch_bounds__(256)
transpose_split_kernel(const float* __restrict__ W,
                       __nv_bfloat16* __restrict__ Th,
                       __nv_bfloat16* __restrict__ Tl)
{
    __shared__ float t[32][33];
    const int tx = threadIdx.x, ty = threadIdx.y;   // (32, 8)
    const int kx = blockIdx.y * 32;                 // K tile
    const int nx = blockIdx.x * 32;                 // N tile
    #pragma unroll
    for (int r = 0; r < 32; r += 8)
        t[ty + r][tx] = W[(size_t)(kx + ty + r) * D_ + nx + tx];
    __syncthreads();
    #pragma unroll
    for (int r = 0; r < 32; r += 8) {
        const int n = nx + ty + r;
        const int k = kx + tx;
        __nv_bfloat16 h, l;
        split_bf16(t[tx][ty + r], h, l);
        Th[(size_t)n * D_ + k] = h;
        Tl[(size_t)n * D_ + k] = l;
    }
}

// ---------------------------------------------------------------------------
// HMMA bf16x3 GEMM via mma.sync (same as round 3, new MODE-1 epilogue)
// MODE 0: C fp32 row-major [M,N]
// MODE 1: C split-bf16 head-split [B,H,S,DEPTH] (Ch/Cl)
// ---------------------------------------------------------------------------
#define LDT       40
#define TILE_B    (128 * LDT * 2)
#define STAGE_B   (4 * TILE_B)
#define GEMM_SMEM (2 * STAGE_B)

template <int MODE>
__global__ void __launch_bounds__(256)
mma_gemm(const __nv_bfloat16* __restrict__ Ah, const __nv_bfloat16* __restrict__ Al,
         const __nv_bfloat16* __restrict__ Bh, const __nv_bfloat16* __restrict__ Bl,
         const float* __restrict__ bias, float* __restrict__ C,
         __nv_bfloat16* __restrict__ Ch, __nv_bfloat16* __restrict__ Cl, float alpha)
{
    extern __shared__ char smem[];
    const uint32_t sb = smem_u32(smem);

    const int tid  = threadIdx.x;
    const int wid  = tid >> 5;
    const int lane = tid & 31;
    const int wm   = wid & 3;
    const int wn   = wid >> 2;
    const int m0   = blockIdx.y * 128;
    const int n0   = blockIdx.x * 128;

    const __nv_bfloat16* srcs[4] = {Ah, Al, Bh, Bl};
    const int rowbase[4] = {m0, m0, n0, n0};

    auto load_stage = [&](int kb, int buf) {
        const uint32_t st = sb + buf * STAGE_B;
        #pragma unroll
        for (int t = 0; t < 4; t++) {
            const __nv_bfloat16* s = srcs[t];
            const int rb = rowbase[t];
            #pragma unroll
            for (int r = 0; r < 2; r++) {
                const int idx  = r * 256 + tid;
                const int row  = idx >> 2;
                const int ch   = idx & 3;
                const __nv_bfloat16* src = s + (size_t)(rb + row) * D_ + kb * 32 + ch * 8;
                const uint32_t dst = st + t * TILE_B + row * (LDT * 2) + ch * 16;
                CP_ASYNC16(dst, src);
            }
        }
        CP_COMMIT();
    };

    float acc[2][8][4];
    #pragma unroll
    for (int i = 0; i < 2; i++)
        #pragma unroll
        for (int j = 0; j < 8; j++)
            #pragma unroll
            for (int v = 0; v < 4; v++)
                acc[i][j][v] = 0.0f;

    load_stage(0, 0);
    load_stage(1, 1);

    const int a_r = lane & 15;
    const int a_c = (lane >> 4) << 3;
    const int b_r = (lane & 7) + ((lane >> 4) << 3);
    const int b_c = ((lane >> 3) & 1) << 3;

    const int NITER = D_ / 32;
    for (int kb = 0; kb < NITER; kb++) {
        const int buf = kb & 1;
        if (kb == NITER - 1) { CP_WAIT(0); } else { CP_WAIT(1); }
        __syncthreads();

        const uint32_t st  = sb + buf * STAGE_B;
        const uint32_t tAh = st;
        const uint32_t tAl = st + TILE_B;
        const uint32_t tBh = st + 2 * TILE_B;
        const uint32_t tBl = st + 3 * TILE_B;

        #pragma unroll
        for (int ks = 0; ks < 32; ks += 16) {
            uint32_t ah[2][4], al_[2][4];
            #pragma unroll
            for (int mf = 0; mf < 2; mf++) {
                const int row = wm * 32 + mf * 16 + a_r;
                const uint32_t off = row * (LDT * 2) + (ks + a_c) * 2;
                LDSM_X4(ah[mf][0], ah[mf][1], ah[mf][2], ah[mf][3], tAh + off);
                LDSM_X4(al_[mf][0], al_[mf][1], al_[mf][2], al_[mf][3], tAl + off);
            }
            uint32_t bh[8][2], bl[8][2];
            #pragma unroll
            for (int gp = 0; gp < 4; gp++) {
                const int row = wn * 64 + gp * 16 + b_r;
                const uint32_t off = row * (LDT * 2) + (ks + b_c) * 2;
                LDSM_X4(bh[2 * gp][0], bh[2 * gp][1], bh[2 * gp + 1][0], bh[2 * gp + 1][1],
                        tBh + off);
                LDSM_X4(bl[2 * gp][0], bl[2 * gp][1], bl[2 * gp + 1][0], bl[2 * gp + 1][1],
                        tBl + off);
            }
            #pragma unroll
            for (int mf = 0; mf < 2; mf++)
                #pragma unroll
                for (int nf = 0; nf < 8; nf++) {
                    MMA_BF16(acc[mf][nf], ah[mf], bh[nf]);
                    MMA_BF16(acc[mf][nf], ah[mf], bl[nf]);
                    MMA_BF16(acc[mf][nf], al_[mf], bh[nf]);
                }
        }
        __syncthreads();
        if (kb + 2 < NITER) load_stage(kb + 2, buf);
    }

    const int er = lane >> 2;
    const int ec = (lane & 3) * 2;
    #pragma unroll
    for (int mf = 0; mf < 2; mf++) {
        #pragma unroll
        for (int nf = 0; nf < 8; nf++) {
            const int n  = n0 + wn * 64 + nf * 8 + ec;
            const float b0 = bias[n], b1 = bias[n + 1];
            #pragma unroll
            for (int half = 0; half < 2; half++) {
                const int m = m0 + wm * 32 + mf * 16 + er + half * 8;
                const float vx = (acc[mf][nf][half * 2 + 0] + b0) * alpha;
                const float vy = (acc[mf][nf][half * 2 + 1] + b1) * alpha;
                if (MODE == 0) {
                    float2 v; v.x = vx; v.y = vy;
                    *reinterpret_cast<float2*>(&C[(size_t)m * D_ + n]) = v;
                } else {
                    const int b  = m >> 11;
                    const int s  = m & 2047;
                    const int h  = n >> 6;
                    const int dd = n & 63;
                    uint32_t hp, lp;
                    split_pack2(vx, vy, hp, lp);
                    const size_t idx = (((size_t)(b * H_ + h)) * S_ + s) * DEPTH + dd;
                    *reinterpret_cast<uint32_t*>(&Ch[idx]) = hp;
                    *reinterpret_cast<uint32_t*>(&Cl[idx]) = lp;
                }
            }
        }
    }
}

// ---------------------------------------------------------------------------
// Flash attention via HMMA, bf16x3 for both QK^T and PV.
// Grid: (S/64, B*H). Block: 128 threads (4 warps; warp w owns q-rows w*16..+15).
// Q pre-scaled by 1/8 in projection. Causal: kt in [0, qt].
// ---------------------------------------------------------------------------
#define ALD       72                       // smem stride in bf16 (144B, conflict-free)
#define ATILE_B   (64 * ALD * 2)           // 9216 bytes per 64x64 tile
#define ASTAGE_B  (4 * ATILE_B)            // Kh, Kl, Vh, Vl = 36864
#define AQ_B      (2 * ATILE_B)            // Qh, Ql = 18432
#define ATTN_SMEM (AQ_B + 2 * ASTAGE_B)    // 92160

__global__ void __launch_bounds__(128)
attn_mma_kernel(const __nv_bfloat16* __restrict__ qh_g, const __nv_bfloat16* __restrict__ ql_g,
                const __nv_bfloat16* __restrict__ kh_g, const __nv_bfloat16* __restrict__ kl_g,
                const __nv_bfloat16* __restrict__ vh_g, const __nv_bfloat16* __restrict__ vl_g,
                __nv_bfloat16* __restrict__ out_hi, __nv_bfloat16* __restrict__ out_lo)
{
    extern __shared__ char smem[];
    const uint32_t sb     = smem_u32(smem);
    const uint32_t sQ     = sb;
    const uint32_t sStage = sb + AQ_B;

    const int tid  = threadIdx.x;
    const int wid  = tid >> 5;
    const int lane = tid & 31;
    const int qt   = blockIdx.x;
    const int bh   = blockIdx.y;
    const int q0   = qt * 64;

    const size_t headbase = (size_t)bh * S_ * DEPTH;

    // ---- Load Q tile (hi+lo) ----
    {
        const __nv_bfloat16* qsrc[2] = {qh_g, ql_g};
        #pragma unroll
        for (int t = 0; t < 2; t++) {
            const __nv_bfloat16* s = qsrc[t] + headbase + (size_t)q0 * DEPTH;
            #pragma unroll
            for (int i = 0; i < 4; i++) {
                const int idx = i * 128 + tid;
                const int row = idx >> 3, ch = idx & 7;
                CP_ASYNC16(sQ + t * ATILE_B + row * (ALD * 2) + ch * 16,
                           s + row * DEPTH + ch * 8);
            }
        }
    }

    const __nv_bfloat16* kvsrc[4] = {kh_g, kl_g, vh_g, vl_g};
    auto load_kv = [&](int kt, int buf) {
        const uint32_t st = sStage + buf * ASTAGE_B;
        const size_t base = headbase + (size_t)kt * 64 * DEPTH;
        #pragma unroll
        for (int t = 0; t < 4; t++) {
            const __nv_bfloat16* s = kvsrc[t] + base;
            #pragma unroll
            for (int i = 0; i < 4; i++) {
                const int idx = i * 128 + tid;
                const int row = idx >> 3, ch = idx & 7;
                CP_ASYNC16(st + t * ATILE_B + row * (ALD * 2) + ch * 16,
                           s + row * DEPTH + ch * 8);
            }
        }
    };

    load_kv(0, 0);
    CP_COMMIT();          // group: Q + stage0
    CP_WAIT(0);
    __syncthreads();

    // ---- Load Q fragments into registers ----
    const int a_r = lane & 15;
    const int a_c = (lane >> 4) << 3;
    uint32_t aqh[4][4], aql[4][4];
    {
        const int row = wid * 16 + a_r;
        #pragma unroll
        for (int t = 0; t < 4; t++) {
            const uint32_t off = row * (ALD * 2) + (t * 16 + a_c) * 2;
            LDSM_X4(aqh[t][0], aqh[t][1], aqh[t][2], aqh[t][3], sQ + off);
            LDSM_X4(aql[t][0], aql[t][1], aql[t][2], aql[t][3], sQ + ATILE_B + off);
        }
    }

    const int b_r = (lane & 7) + ((lane >> 4) << 3);
    const int b_c = ((lane >> 3) & 1) << 3;
    const int v_r = (lane & 7) + (((lane >> 3) & 1) << 3);
    const int v_c = (lane >> 4) << 3;
    const int er  = lane >> 2;
    const int ec  = (lane & 3) * 2;

    float oacc[8][4];
    #pragma unroll
    for (int j = 0; j < 8; j++)
        #pragma unroll
        for (int v = 0; v < 4; v++) oacc[j][v] = 0.0f;
    float m0 = -1e30f, m1 = -1e30f, l0 = 0.0f, l1 = 0.0f;

    for (int kt = 0; kt <= qt; kt++) {
        const int buf = kt & 1;
        if (kt < qt) { load_kv(kt + 1, buf ^ 1); CP_COMMIT(); CP_WAIT(1); }
        else         { CP_WAIT(0); }
        __syncthreads();

        const uint32_t st  = sStage + buf * ASTAGE_B;
        const uint32_t tKh = st;
        const uint32_t tKl = st + ATILE_B;
        const uint32_t tVh = st + 2 * ATILE_B;
        const uint32_t tVl = st + 3 * ATILE_B;

        // ---- Scores: S = Qh*Kh + Qh*Kl + Ql*Kh ----
        float sacc[8][4];
        #pragma unroll
        for (int j = 0; j < 8; j++)
            #pragma unroll
            for (int v = 0; v < 4; v++) sacc[j][v] = 0.0f;

        #pragma unroll
        for (int t = 0; t < 4; t++) {
            uint32_t kbh[8][2], kbl[8][2];
            #pragma unroll
            for (int g = 0; g < 4; g++) {
                const int row = g * 16 + b_r;
                const uint32_t off = row * (ALD * 2) + (t * 16 + b_c) * 2;
                LDSM_X4(kbh[2 * g][0], kbh[2 * g][1], kbh[2 * g + 1][0], kbh[2 * g + 1][1],
                        tKh + off);
                LDSM_X4(kbl[2 * g][0], kbl[2 * g][1], kbl[2 * g + 1][0], kbl[2 * g + 1][1],
                        tKl + off);
            }
            #pragma unroll
            for (int nf = 0; nf < 8; nf++) {
                MMA_BF16(sacc[nf], aqh[t], kbh[nf]);
                MMA_BF16(sacc[nf], aqh[t], kbl[nf]);
                MMA_BF16(sacc[nf], aql[t], kbh[nf]);
            }
        }

        // ---- Causal mask on diagonal tile ----
        if (kt == qt) {
            const int r0_ = wid * 16 + er;
            const int r1_ = r0_ + 8;
            #pragma unroll
            for (int nf = 0; nf < 8; nf++) {
                const int c0_ = nf * 8 + ec;
                if (c0_ > r0_)     sacc[nf][0] = -1e30f;
                if (c0_ + 1 > r0_) sacc[nf][1] = -1e30f;
                if (c0_ > r1_)     sacc[nf][2] = -1e30f;
                if (c0_ + 1 > r1_) sacc[nf][3] = -1e30f;
            }
        }

        // ---- Online softmax (rows er, er+8) ----
        float mn0 = -1e30f, mn1 = -1e30f;
        #pragma unroll
        for (int nf = 0; nf < 8; nf++) {
            mn0 = fmaxf(mn0, fmaxf(sacc[nf][0], sacc[nf][1]));
            mn1 = fmaxf(mn1, fmaxf(sacc[nf][2], sacc[nf][3]));
        }
        mn0 = fmaxf(mn0, __shfl_xor_sync(0xffffffffu, mn0, 1));
        mn0 = fmaxf(mn0, __shfl_xor_sync(0xffffffffu, mn0, 2));
        mn1 = fmaxf(mn1, __shfl_xor_sync(0xffffffffu, mn1, 1));
        mn1 = fmaxf(mn1, __shfl_xor_sync(0xffffffffu, mn1, 2));

        const float nm0 = fmaxf(m0, mn0);
        const float nm1 = fmaxf(m1, mn1);
        const float corr0 = __expf(m0 - nm0);
        const float corr1 = __expf(m1 - nm1);
        m0 = nm0; m1 = nm1;

        float rs0 = 0.0f, rs1 = 0.0f;
        #pragma unroll
        for (int nf = 0; nf < 8; nf++) {
            sacc[nf][0] = __expf(sacc[nf][0] - nm0);
            sacc[nf][1] = __expf(sacc[nf][1] - nm0);
            sacc[nf][2] = __expf(sacc[nf][2] - nm1);
            sacc[nf][3] = __expf(sacc[nf][3] - nm1);
            rs0 += sacc[nf][0] + sacc[nf][1];
            rs1 += sacc[nf][2] + sacc[nf][3];
        }
        rs0 += __shfl_xor_sync(0xffffffffu, rs0, 1);
        rs0 += __shfl_xor_sync(0xffffffffu, rs0, 2);
        rs1 += __shfl_xor_sync(0xffffffffu, rs1, 1);
        rs1 += __shfl_xor_sync(0xffffffffu, rs1, 2);
        l0 = l0 * corr0 + rs0;
        l1 = l1 * corr1 + rs1;

        #pragma unroll
        for (int j = 0; j < 8; j++) {
            oacc[j][0] *= corr0; oacc[j][1] *= corr0;
            oacc[j][2] *= corr1; oacc[j][3] *= corr1;
        }

        // ---- P -> split-bf16 A fragments ----
        uint32_t ph[4][4], pl[4][4];
        #pragma unroll
        for (int t = 0; t < 4; t++) {
            split_pack2(sacc[2 * t][0],     sacc[2 * t][1],     ph[t][0], pl[t][0]);
            split_pack2(sacc[2 * t][2],     sacc[2 * t][3],     ph[t][1], pl[t][1]);
            split_pack2(sacc[2 * t + 1][0], sacc[2 * t + 1][1], ph[t][2], pl[t][2]);
            split_pack2(sacc[2 * t + 1][2], sacc[2 * t + 1][3], ph[t][3], pl[t][3]);
        }

        // ---- O += Ph*Vh + Ph*Vl + Pl*Vh ----
        #pragma unroll
        for (int t = 0; t < 4; t++) {
            uint32_t vbh[8][2], vbl[8][2];
            #pragma unroll
            for (int g = 0; g < 4; g++) {
                const int row = t * 16 + v_r;
                const uint32_t off = row * (ALD * 2) + (g * 16 + v_c) * 2;
                LDSM_X4_T(vbh[2 * g][0], vbh[2 * g][1], vbh[2 * g + 1][0], vbh[2 * g + 1][1],
                          tVh + off);
                LDSM_X4_T(vbl[2 * g][0], vbl[2 * g][1], vbl[2 * g + 1][0], vbl[2 * g + 1][1],
                          tVl + off);
            }
            #pragma unroll
            for (int df = 0; df < 8; df++) {
                MMA_BF16(oacc[df], ph[t], vbh[df]);
                MMA_BF16(oacc[df], ph[t], vbl[df]);
                MMA_BF16(oacc[df], pl[t], vbh[df]);
            }
        }
        __syncthreads();
    }

    // ---- Normalize, split, write out [B,S,D] ----
    const int b = bh >> 4;
    const int h = bh & 15;
    const float inv0 = 1.0f / l0;
    const float inv1 = 1.0f / l1;
    const int s0 = q0 + wid * 16 + er;
    #pragma unroll
    for (int df = 0; df < 8; df++) {
        const int col = h * DEPTH + df * 8 + ec;
        {
            uint32_t hp, lp;
            split_pack2(oacc[df][0] * inv0, oacc[df][1] * inv0, hp, lp);
            const size_t idx = ((size_t)b * S_ + s0) * D_ + col;
            *reinterpret_cast<uint32_t*>(&out_hi[idx]) = hp;
            *reinterpret_cast<uint32_t*>(&out_lo[idx]) = lp;
        }
        {
            uint32_t hp, lp;
            split_pack2(oacc[df][2] * inv1, oacc[df][3] * inv1, hp, lp);
            const size_t idx = ((size_t)b * S_ + s0 + 8) * D_ + col;
            *reinterpret_cast<uint32_t*>(&out_hi[idx]) = hp;
            *reinterpret_cast<uint32_t*>(&out_lo[idx]) = lp;
        }
    }
}

// ---------------------------------------------------------------------------
// Launch
// ---------------------------------------------------------------------------
extern "C" void kernel_launch(void* const* d_in, const int* in_sizes, int n_in,
                              void* d_out, int out_size)
{
    (void)in_sizes; (void)n_in; (void)out_size;
    const float* v_in = (const float*)d_in[0];
    const float* k_in = (const float*)d_in[1];
    const float* q_in = (const float*)d_in[2];
    const float* wq = (const float*)d_in[4];
    const float* bq = (const float*)d_in[5];
    const float* wk = (const float*)d_in[6];
    const float* bk = (const float*)d_in[7];
    const float* wv = (const float*)d_in[8];
    const float* bv = (const float*)d_in[9];
    const float* wo = (const float*)d_in[10];
    const float* bo = (const float*)d_in[11];
    float* out = (float*)d_out;

    __nv_bfloat16 *ih, *il, *wh, *wl, *ah, *al;
    __nv_bfloat16 *qh, *ql, *kh, *kl, *vh, *vl;
    cudaGetSymbolAddress((void**)&ih, g_in_hi);
    cudaGetSymbolAddress((void**)&il, g_in_lo);
    cudaGetSymbolAddress((void**)&wh, g_wt_hi);
    cudaGetSymbolAddress((void**)&wl, g_wt_lo);
    cudaGetSymbolAddress((void**)&ah, g_attn_hi);
    cudaGetSymbolAddress((void**)&al, g_attn_lo);
    cudaGetSymbolAddress((void**)&qh, g_qh);
    cudaGetSymbolAddress((void**)&ql, g_ql);
    cudaGetSymbolAddress((void**)&kh, g_kh);
    cudaGetSymbolAddress((void**)&kl, g_kl);
    cudaGetSymbolAddress((void**)&vh, g_vh);
    cudaGetSymbolAddress((void**)&vl, g_vl);

    static bool attr_set = false;
    if (!attr_set) {
        cudaFuncSetAttribute(attn_mma_kernel,
                             cudaFuncAttributeMaxDynamicSharedMemorySize, ATTN_SMEM);
        cudaFuncSetAttribute(mma_gemm<0>,
                             cudaFuncAttributeMaxDynamicSharedMemorySize, GEMM_SMEM);
        cudaFuncSetAttribute(mma_gemm<1>,
                             cudaFuncAttributeMaxDynamicSharedMemorySize, GEMM_SMEM);
        attr_set = true;
    }

    const size_t ND = (size_t)MTOK * D_;
    const size_t WD = (size_t)D_ * D_;

    // 1) Split inputs (v,k,q) into bf16 hi/lo
    const int n4 = (int)(ND / 4);
    const int cgrid = (n4 + 255) / 256;
    convert_split_kernel<<<cgrid, 256>>>(v_in, ih + 0 * ND, il + 0 * ND, n4);
    convert_split_kernel<<<cgrid, 256>>>(k_in, ih + 1 * ND, il + 1 * ND, n4);
    convert_split_kernel<<<cgrid, 256>>>(q_in, ih + 2 * ND, il + 2 * ND, n4);

    // 2) Transpose + split weights (wq, wk, wv, wo)
    const dim3 tgrid(32, 32), tblock(32, 8);
    transpose_split_kernel<<<tgrid, tblock>>>(wq, wh + 0 * WD, wl + 0 * WD);
    transpose_split_kernel<<<tgrid, tblock>>>(wk, wh + 1 * WD, wl + 1 * WD);
    transpose_split_kernel<<<tgrid, tblock>>>(wv, wh + 2 * WD, wl + 2 * WD);
    transpose_split_kernel<<<tgrid, tblock>>>(wo, wh + 3 * WD, wl + 3 * WD);

    // 3) Projections via HMMA -> split-bf16 head-split outputs; Q pre-scaled 1/8
    const dim3 ggrid(D_ / 128, MTOK / 128);   // (8, 64)
    mma_gemm<1><<<ggrid, 256, GEMM_SMEM>>>(ih + 2 * ND, il + 2 * ND,
                                           wh + 0 * WD, wl + 0 * WD, bq,
                                           nullptr, qh, ql, 0.125f);
    mma_gemm<1><<<ggrid, 256, GEMM_SMEM>>>(ih + 1 * ND, il + 1 * ND,
                                           wh + 1 * WD, wl + 1 * WD, bk,
                                           nullptr, kh, kl, 1.0f);
    mma_gemm<1><<<ggrid, 256, GEMM_SMEM>>>(ih + 0 * ND, il + 0 * ND,
                                           wh + 2 * WD, wl + 2 * WD, bv,
                                           nullptr, vh, vl, 1.0f);

    // 4) Causal flash attention (HMMA) -> split-bf16 [B,S,D]
    const dim3 attn_grid(S_ / 64, B_ * H_);   // (32, 64)
    attn_mma_kernel<<<attn_grid, 128, ATTN_SMEM>>>(qh, ql, kh, kl, vh, vl, ah, al);

    // 5) Output projection (fp32 out)
    mma_gemm<0><<<ggrid, 256, GEMM_SMEM>>>(ah, al, wh + 3 * WD, wl + 3 * WD, bo,
                                           out, nullptr, nullptr, 1.0f);
}

// round 5
// speedup vs baseline: 3.2300x; 1.0736x over previous
#include <cuda_runtime.h>
#include <cuda_bf16.h>
#include <math.h>
#include <stdint.h>

// Problem constants
#define B_    4
#define S_    2048
#define D_    1024
#define H_    16
#define DEPTH 64
#define MTOK  (B_ * S_)   // 8192 token rows

// ---------------------------------------------------------------------------
// Scratch (device globals; no allocation allowed)
// ---------------------------------------------------------------------------
// split-bf16 inputs (v,k,q order matches d_in)
__device__ __nv_bfloat16 g_in_hi[3][MTOK * D_];
__device__ __nv_bfloat16 g_in_lo[3][MTOK * D_];
// split-bf16 transposed weights [N,K] (wq,wk,wv,wo)
__device__ __nv_bfloat16 g_wt_hi[4][D_ * D_];
__device__ __nv_bfloat16 g_wt_lo[4][D_ * D_];
// projected q/k/v, split bf16, head-split [B,H,S,64]
__device__ __nv_bfloat16 g_qh[MTOK * D_];
__device__ __nv_bfloat16 g_ql[MTOK * D_];
__device__ __nv_bfloat16 g_kh[MTOK * D_];
__device__ __nv_bfloat16 g_kl[MTOK * D_];
__device__ __nv_bfloat16 g_vh[MTOK * D_];
__device__ __nv_bfloat16 g_vl[MTOK * D_];
// attention output, split-bf16 [B,S,D]
__device__ __nv_bfloat16 g_attn_hi[MTOK * D_];
__device__ __nv_bfloat16 g_attn_lo[MTOK * D_];

// ---------------------------------------------------------------------------
// PTX helpers (sm_103 base target: mma.sync / ldmatrix / cp.async only)
// ---------------------------------------------------------------------------
__device__ __forceinline__ uint32_t smem_u32(const void* p) {
    uint32_t a;
    asm("{ .reg .u64 t; cvta.to.shared.u64 t, %1; cvt.u32.u64 %0, t; }"
        : "=r"(a) : "l"(p));
    return a;
}

#define CP_ASYNC16(dst_u32, src_ptr) \
    asm volatile("cp.async.cg.shared.global [%0], [%1], 16;" \
                 :: "r"(dst_u32), "l"(src_ptr) : "memory")
#define CP_COMMIT() asm volatile("cp.async.commit_group;" ::: "memory")
#define CP_WAIT(n)  asm volatile("cp.async.wait_group %0;" :: "n"(n) : "memory")

#define LDSM_X4(r0, r1, r2, r3, addr) \
    asm volatile("ldmatrix.sync.aligned.m8n8.x4.shared.b16 {%0,%1,%2,%3}, [%4];" \
                 : "=r"(r0), "=r"(r1), "=r"(r2), "=r"(r3) : "r"(addr))

#define LDSM_X4_T(r0, r1, r2, r3, addr) \
    asm volatile("ldmatrix.sync.aligned.m8n8.x4.trans.shared.b16 {%0,%1,%2,%3}, [%4];" \
                 : "=r"(r0), "=r"(r1), "=r"(r2), "=r"(r3) : "r"(addr))

#define MMA_BF16(d, a, b) \
    asm volatile("mma.sync.aligned.m16n8k16.row.col.f32.bf16.bf16.f32 " \
                 "{%0,%1,%2,%3}, {%4,%5,%6,%7}, {%8,%9}, {%0,%1,%2,%3};" \
                 : "+f"((d)[0]), "+f"((d)[1]), "+f"((d)[2]), "+f"((d)[3]) \
                 : "r"((a)[0]), "r"((a)[1]), "r"((a)[2]), "r"((a)[3]), \
                   "r"((b)[0]), "r"((b)[1]))

__device__ __forceinline__ void split_bf16(float x, __nv_bfloat16& h, __nv_bfloat16& l) {
    h = __float2bfloat16(x);
    l = __float2bfloat16(x - __bfloat162float(h));
}

__device__ __forceinline__ void split_pack2(float x, float y, uint32_t& hi, uint32_t& lo) {
    __nv_bfloat16 xh, xl, yh, yl;
    split_bf16(x, xh, xl);
    split_bf16(y, yh, yl);
    __nv_bfloat162 h2; h2.x = xh; h2.y = yh;
    __nv_bfloat162 l2; l2.x = xl; l2.y = yl;
    hi = *reinterpret_cast<uint32_t*>(&h2);
    lo = *reinterpret_cast<uint32_t*>(&l2);
}

// ---------------------------------------------------------------------------
// Conversion kernels
// ---------------------------------------------------------------------------
__global__ void __launch_bounds__(256)
convert_split_kernel(const float* __restrict__ in,
                     __nv_bfloat16* __restrict__ hi,
                     __nv_bfloat16* __restrict__ lo, int n4)
{
    int i = blockIdx.x * blockDim.x + threadIdx.x;
    if (i >= n4) return;
    float4 v = reinterpret_cast<const float4*>(in)[i];
    uint32_t h0, l0, h1, l1;
    split_pack2(v.x, v.y, h0, l0);
    split_pack2(v.z, v.w, h1, l1);
    uint32_t* hp = reinterpret_cast<uint32_t*>(hi);
    uint32_t* lp = reinterpret_cast<uint32_t*>(lo);
    hp[2 * i] = h0; hp[2 * i + 1] = h1;
    lp[2 * i] = l0; lp[2 * i + 1] = l1;
}

// W[K,N] fp32 -> Wt_hi/lo [N,K] bf16 (transpose + split)
__global__ void __launch_bounds__(256)
transpose_split_kernel(const float* __restrict__ W,
                       __nv_bfloat16* __restrict__ Th,
                       __nv_bfloat16* __restrict__ Tl)
{
    __shared__ float t[32][33];
    const int tx = threadIdx.x, ty = threadIdx.y;   // (32, 8)
    const int kx = blockIdx.y * 32;
    const int nx = blockIdx.x * 32;
    #pragma unroll
    for (int r = 0; r < 32; r += 8)
        t[ty + r][tx] = W[(size_t)(kx + ty + r) * D_ + nx + tx];
    __syncthreads();
    #pragma unroll
    for (int r = 0; r < 32; r += 8) {
        const int n = nx + ty + r;
        const int k = kx + tx;
        __nv_bfloat16 h, l;
        split_bf16(t[tx][ty + r], h, l);
        Th[(size_t)n * D_ + k] = h;
        Tl[(size_t)n * D_ + k] = l;
    }
}

// ---------------------------------------------------------------------------
// HMMA bf16x3 GEMM body (shared by QKV-fused kernel and output projection).
//   128x128 CTA tile, 4 warps (2x2), 64x64 warp tiles, K-block 32, 2 stages.
//   MMA:LDSM ratio 6:1 -> tensor-bound.
// MODE 0: C fp32 row-major [M,N]
// MODE 1: C split-bf16 head-split [B,H,S,DEPTH] (Ch/Cl)
// ---------------------------------------------------------------------------
#define LDT       40                       // smem stride in bf16 (80B row)
#define TILE_B    (128 * LDT * 2)          // 10240 bytes
#define STAGE_B   (4 * TILE_B)             // 40960
#define GEMM_SMEM (2 * STAGE_B)            // 81920

template <int MODE>
__device__ __forceinline__ void
gemm_body(const __nv_bfloat16* __restrict__ Ah, const __nv_bfloat16* __restrict__ Al,
          const __nv_bfloat16* __restrict__ Bh, const __nv_bfloat16* __restrict__ Bl,
          const float* __restrict__ bias, float* __restrict__ C,
          __nv_bfloat16* __restrict__ Ch, __nv_bfloat16* __restrict__ Cl, float alpha)
{
    extern __shared__ char smem[];
    const uint32_t sb = smem_u32(smem);

    const int tid  = threadIdx.x;        // 0..127
    const int wid  = tid >> 5;           // 0..3
    const int lane = tid & 31;
    const int wm   = wid & 1;            // warp row -> 64 rows
    const int wn   = wid >> 1;           // warp col -> 64 cols
    const int m0   = blockIdx.y * 128;
    const int n0   = blockIdx.x * 128;

    const __nv_bfloat16* srcs[4] = {Ah, Al, Bh, Bl};
    const int rowbase[4] = {m0, m0, n0, n0};

    auto load_stage = [&](int kb, int buf) {
        const uint32_t st = sb + buf * STAGE_B;
        #pragma unroll
        for (int t = 0; t < 4; t++) {
            const __nv_bfloat16* s = srcs[t];
            const int rb = rowbase[t];
            #pragma unroll
            for (int r = 0; r < 4; r++) {
                const int idx  = r * 128 + tid;
                const int row  = idx >> 2;
                const int ch   = idx & 3;
                const __nv_bfloat16* src = s + (size_t)(rb + row) * D_ + kb * 32 + ch * 8;
                const uint32_t dst = st + t * TILE_B + row * (LDT * 2) + ch * 16;
                CP_ASYNC16(dst, src);
            }
        }
        CP_COMMIT();
    };

    float acc[4][8][4];
    #pragma unroll
    for (int i = 0; i < 4; i++)
        #pragma unroll
        for (int j = 0; j < 8; j++)
            #pragma unroll
            for (int v = 0; v < 4; v++)
                acc[i][j][v] = 0.0f;

    load_stage(0, 0);
    load_stage(1, 1);

    const int a_r = lane & 15;
    const int a_c = (lane >> 4) << 3;
    const int b_r = (lane & 7) + ((lane >> 4) << 3);
    const int b_c = ((lane >> 3) & 1) << 3;

    const int NITER = D_ / 32;    // 32
    for (int kb = 0; kb < NITER; kb++) {
        const int buf = kb & 1;
        if (kb == NITER - 1) { CP_WAIT(0); } else { CP_WAIT(1); }
        __syncthreads();

        const uint32_t st  = sb + buf * STAGE_B;
        const uint32_t tAh = st;
        const uint32_t tAl = st + TILE_B;
        const uint32_t tBh = st + 2 * TILE_B;
        const uint32_t tBl = st + 3 * TILE_B;

        #pragma unroll
        for (int ks = 0; ks < 32; ks += 16) {
            uint32_t ah[4][4], al_[4][4];
            #pragma unroll
            for (int mf = 0; mf < 4; mf++) {
                const int row = wm * 64 + mf * 16 + a_r;
                const uint32_t off = row * (LDT * 2) + (ks + a_c) * 2;
                LDSM_X4(ah[mf][0], ah[mf][1], ah[mf][2], ah[mf][3], tAh + off);
                LDSM_X4(al_[mf][0], al_[mf][1], al_[mf][2], al_[mf][3], tAl + off);
            }
            uint32_t bh[8][2], bl[8][2];
            #pragma unroll
            for (int gp = 0; gp < 4; gp++) {
                const int row = wn * 64 + gp * 16 + b_r;
                const uint32_t off = row * (LDT * 2) + (ks + b_c) * 2;
                LDSM_X4(bh[2 * gp][0], bh[2 * gp][1], bh[2 * gp + 1][0], bh[2 * gp + 1][1],
                        tBh + off);
                LDSM_X4(bl[2 * gp][0], bl[2 * gp][1], bl[2 * gp + 1][0], bl[2 * gp + 1][1],
                        tBl + off);
            }
            #pragma unroll
            for (int mf = 0; mf < 4; mf++)
                #pragma unroll
                for (int nf = 0; nf < 8; nf++) {
                    MMA_BF16(acc[mf][nf], ah[mf], bh[nf]);
                    MMA_BF16(acc[mf][nf], ah[mf], bl[nf]);
                    MMA_BF16(acc[mf][nf], al_[mf], bh[nf]);
                }
        }
        __syncthreads();
        if (kb + 2 < NITER) load_stage(kb + 2, buf);
    }

    const int er = lane >> 2;
    const int ec = (lane & 3) * 2;
    #pragma unroll
    for (int mf = 0; mf < 4; mf++) {
        #pragma unroll
        for (int nf = 0; nf < 8; nf++) {
            const int n  = n0 + wn * 64 + nf * 8 + ec;
            const float b0 = bias[n], b1 = bias[n + 1];
            #pragma unroll
            for (int half = 0; half < 2; half++) {
                const int m = m0 + wm * 64 + mf * 16 + er + half * 8;
                const float vx = (acc[mf][nf][half * 2 + 0] + b0) * alpha;
                const float vy = (acc[mf][nf][half * 2 + 1] + b1) * alpha;
                if (MODE == 0) {
                    float2 v; v.x = vx; v.y = vy;
                    *reinterpret_cast<float2*>(&C[(size_t)m * D_ + n]) = v;
                } else {
                    const int b  = m >> 11;
                    const int s  = m & 2047;
                    const int h  = n >> 6;
                    const int dd = n & 63;
                    uint32_t hp, lp;
                    split_pack2(vx, vy, hp, lp);
                    const size_t idx = (((size_t)(b * H_ + h)) * S_ + s) * DEPTH + dd;
                    *reinterpret_cast<uint32_t*>(&Ch[idx]) = hp;
                    *reinterpret_cast<uint32_t*>(&Cl[idx]) = lp;
                }
            }
        }
    }
}

// Fused QKV projection: grid.z selects {q,k,v}. Q pre-scaled by 1/8.
__global__ void __launch_bounds__(128)
qkv_gemm(const float* __restrict__ bq, const float* __restrict__ bk,
         const float* __restrict__ bv)
{
    const int z = blockIdx.z;
    if (z == 0) {
        gemm_body<1>(g_in_hi[2], g_in_lo[2], g_wt_hi[0], g_wt_lo[0],
                     bq, nullptr, g_qh, g_ql, 0.125f);
    } else if (z == 1) {
        gemm_body<1>(g_in_hi[1], g_in_lo[1], g_wt_hi[1], g_wt_lo[1],
                     bk, nullptr, g_kh, g_kl, 1.0f);
    } else {
        gemm_body<1>(g_in_hi[0], g_in_lo[0], g_wt_hi[2], g_wt_lo[2],
                     bv, nullptr, g_vh, g_vl, 1.0f);
    }
}

// Output projection: attn(split-bf16) @ wo + bo -> fp32 out
__global__ void __launch_bounds__(128)
out_gemm(const float* __restrict__ bo, float* __restrict__ C)
{
    gemm_body<0>(g_attn_hi, g_attn_lo, g_wt_hi[3], g_wt_lo[3],
                 bo, C, nullptr, nullptr, 1.0f);
}

// ---------------------------------------------------------------------------
// Flash attention via HMMA, bf16x3 for both QK^T and PV. (unchanged from R4)
// ---------------------------------------------------------------------------
#define ALD       72
#define ATILE_B   (64 * ALD * 2)
#define ASTAGE_B  (4 * ATILE_B)
#define AQ_B      (2 * ATILE_B)
#define ATTN_SMEM (AQ_B + 2 * ASTAGE_B)

__global__ void __launch_bounds__(128)
attn_mma_kernel(const __nv_bfloat16* __restrict__ qh_g, const __nv_bfloat16* __restrict__ ql_g,
                const __nv_bfloat16* __restrict__ kh_g, const __nv_bfloat16* __restrict__ kl_g,
                const __nv_bfloat16* __restrict__ vh_g, const __nv_bfloat16* __restrict__ vl_g,
                __nv_bfloat16* __restrict__ out_hi, __nv_bfloat16* __restrict__ out_lo)
{
    extern __shared__ char smem[];
    const uint32_t sb     = smem_u32(smem);
    const uint32_t sQ     = sb;
    const uint32_t sStage = sb + AQ_B;

    const int tid  = threadIdx.x;
    const int wid  = tid >> 5;
    const int lane = tid & 31;
    const int qt   = blockIdx.x;
    const int bh   = blockIdx.y;
    const int q0   = qt * 64;

    const size_t headbase = (size_t)bh * S_ * DEPTH;

    {
        const __nv_bfloat16* qsrc[2] = {qh_g, ql_g};
        #pragma unroll
        for (int t = 0; t < 2; t++) {
            const __nv_bfloat16* s = qsrc[t] + headbase + (size_t)q0 * DEPTH;
            #pragma unroll
            for (int i = 0; i < 4; i++) {
                const int idx = i * 128 + tid;
                const int row = idx >> 3, ch = idx & 7;
                CP_ASYNC16(sQ + t * ATILE_B + row * (ALD * 2) + ch * 16,
                           s + row * DEPTH + ch * 8);
            }
        }
    }

    const __nv_bfloat16* kvsrc[4] = {kh_g, kl_g, vh_g, vl_g};
    auto load_kv = [&](int kt, int buf) {
        const uint32_t st = sStage + buf * ASTAGE_B;
        const size_t base = headbase + (size_t)kt * 64 * DEPTH;
        #pragma unroll
        for (int t = 0; t < 4; t++) {
            const __nv_bfloat16* s = kvsrc[t] + base;
            #pragma unroll
            for (int i = 0; i < 4; i++) {
                const int idx = i * 128 + tid;
                const int row = idx >> 3, ch = idx & 7;
                CP_ASYNC16(st + t * ATILE_B + row * (ALD * 2) + ch * 16,
                           s + row * DEPTH + ch * 8);
            }
        }
    };

    load_kv(0, 0);
    CP_COMMIT();
    CP_WAIT(0);
    __syncthreads();

    const int a_r = lane & 15;
    const int a_c = (lane >> 4) << 3;
    uint32_t aqh[4][4], aql[4][4];
    {
        const int row = wid * 16 + a_r;
        #pragma unroll
        for (int t = 0; t < 4; t++) {
            const uint32_t off = row * (ALD * 2) + (t * 16 + a_c) * 2;
            LDSM_X4(aqh[t][0], aqh[t][1], aqh[t][2], aqh[t][3], sQ + off);
            LDSM_X4(aql[t][0], aql[t][1], aql[t][2], aql[t][3], sQ + ATILE_B + off);
        }
    }

    const int b_r = (lane & 7) + ((lane >> 4) << 3);
    const int b_c = ((lane >> 3) & 1) << 3;
    const int v_r = (lane & 7) + (((lane >> 3) & 1) << 3);
    const int v_c = (lane >> 4) << 3;
    const int er  = lane >> 2;
    const int ec  = (lane & 3) * 2;

    float oacc[8][4];
    #pragma unroll
    for (int j = 0; j < 8; j++)
        #pragma unroll
        for (int v = 0; v < 4; v++) oacc[j][v] = 0.0f;
    float m0 = -1e30f, m1 = -1e30f, l0 = 0.0f, l1 = 0.0f;

    for (int kt = 0; kt <= qt; kt++) {
        const int buf = kt & 1;
        if (kt < qt) { load_kv(kt + 1, buf ^ 1); CP_COMMIT(); CP_WAIT(1); }
        else         { CP_WAIT(0); }
        __syncthreads();

        const uint32_t st  = sStage + buf * ASTAGE_B;
        const uint32_t tKh = st;
        const uint32_t tKl = st + ATILE_B;
        const uint32_t tVh = st + 2 * ATILE_B;
        const uint32_t tVl = st + 3 * ATILE_B;

        float sacc[8][4];
        #pragma unroll
        for (int j = 0; j < 8; j++)
            #pragma unroll
            for (int v = 0; v < 4; v++) sacc[j][v] = 0.0f;

        #pragma unroll
        for (int t = 0; t < 4; t++) {
            uint32_t kbh[8][2], kbl[8][2];
            #pragma unroll
            for (int g = 0; g < 4; g++) {
                const int row = g * 16 + b_r;
                const uint32_t off = row * (ALD * 2) + (t * 16 + b_c) * 2;
                LDSM_X4(kbh[2 * g][0], kbh[2 * g][1], kbh[2 * g + 1][0], kbh[2 * g + 1][1],
                        tKh + off);
                LDSM_X4(kbl[2 * g][0], kbl[2 * g][1], kbl[2 * g + 1][0], kbl[2 * g + 1][1],
                        tKl + off);
            }
            #pragma unroll
            for (int nf = 0; nf < 8; nf++) {
                MMA_BF16(sacc[nf], aqh[t], kbh[nf]);
                MMA_BF16(sacc[nf], aqh[t], kbl[nf]);
                MMA_BF16(sacc[nf], aql[t], kbh[nf]);
            }
        }

        if (kt == qt) {
            const int r0_ = wid * 16 + er;
            const int r1_ = r0_ + 8;
            #pragma unroll
            for (int nf = 0; nf < 8; nf++) {
                const int c0_ = nf * 8 + ec;
                if (c0_ > r0_)     sacc[nf][0] = -1e30f;
                if (c0_ + 1 > r0_) sacc[nf][1] = -1e30f;
                if (c0_ > r1_)     sacc[nf][2] = -1e30f;
                if (c0_ + 1 > r1_) sacc[nf][3] = -1e30f;
            }
        }

        float mn0 = -1e30f, mn1 = -1e30f;
        #pragma unroll
        for (int nf = 0; nf < 8; nf++) {
            mn0 = fmaxf(mn0, fmaxf(sacc[nf][0], sacc[nf][1]));
            mn1 = fmaxf(mn1, fmaxf(sacc[nf][2], sacc[nf][3]));
        }
        mn0 = fmaxf(mn0, __shfl_xor_sync(0xffffffffu, mn0, 1));
        mn0 = fmaxf(mn0, __shfl_xor_sync(0xffffffffu, mn0, 2));
        mn1 = fmaxf(mn1, __shfl_xor_sync(0xffffffffu, mn1, 1));
        mn1 = fmaxf(mn1, __shfl_xor_sync(0xffffffffu, mn1, 2));

        const float nm0 = fmaxf(m0, mn0);
        const float nm1 = fmaxf(m1, mn1);
        const float corr0 = __expf(m0 - nm0);
        const float corr1 = __expf(m1 - nm1);
        m0 = nm0; m1 = nm1;

        float rs0 = 0.0f, rs1 = 0.0f;
        #pragma unroll
        for (int nf = 0; nf < 8; nf++) {
            sacc[nf][0] = __expf(sacc[nf][0] - nm0);
            sacc[nf][1] = __expf(sacc[nf][1] - nm0);
            sacc[nf][2] = __expf(sacc[nf][2] - nm1);
            sacc[nf][3] = __expf(sacc[nf][3] - nm1);
            rs0 += sacc[nf][0] + sacc[nf][1];
            rs1 += sacc[nf][2] + sacc[nf][3];
        }
        rs0 += __shfl_xor_sync(0xffffffffu, rs0, 1);
        rs0 += __shfl_xor_sync(0xffffffffu, rs0, 2);
        rs1 += __shfl_xor_sync(0xffffffffu, rs1, 1);
        rs1 += __shfl_xor_sync(0xffffffffu, rs1, 2);
        l0 = l0 * corr0 + rs0;
        l1 = l1 * corr1 + rs1;

        #pragma unroll
        for (int j = 0; j < 8; j++) {
            oacc[j][0] *= corr0; oacc[j][1] *= corr0;
            oacc[j][2] *= corr1; oacc[j][3] *= corr1;
        }

        uint32_t ph[4][4], pl[4][4];
        #pragma unroll
        for (int t = 0; t < 4; t++) {
            split_pack2(sacc[2 * t][0],     sacc[2 * t][1],     ph[t][0], pl[t][0]);
            split_pack2(sacc[2 * t][2],     sacc[2 * t][3],     ph[t][1], pl[t][1]);
            split_pack2(sacc[2 * t + 1][0], sacc[2 * t + 1][1], ph[t][2], pl[t][2]);
            split_pack2(sacc[2 * t + 1][2], sacc[2 * t + 1][3], ph[t][3], pl[t][3]);
        }

        #pragma unroll
        for (int t = 0; t < 4; t++) {
            uint32_t vbh[8][2], vbl[8][2];
            #pragma unroll
            for (int g = 0; g < 4; g++) {
                const int row = t * 16 + v_r;
                const uint32_t off = row * (ALD * 2) + (g * 16 + v_c) * 2;
                LDSM_X4_T(vbh[2 * g][0], vbh[2 * g][1], vbh[2 * g + 1][0], vbh[2 * g + 1][1],
                          tVh + off);
                LDSM_X4_T(vbl[2 * g][0], vbl[2 * g][1], vbl[2 * g + 1][0], vbl[2 * g + 1][1],
                          tVl + off);
            }
            #pragma unroll
            for (int df = 0; df < 8; df++) {
                MMA_BF16(oacc[df], ph[t], vbh[df]);
                MMA_BF16(oacc[df], ph[t], vbl[df]);
                MMA_BF16(oacc[df], pl[t], vbh[df]);
            }
        }
        __syncthreads();
    }

    const int b = bh >> 4;
    const int h = bh & 15;
    const float inv0 = 1.0f / l0;
    const float inv1 = 1.0f / l1;
    const int s0 = q0 + wid * 16 + er;
    #pragma unroll
    for (int df = 0; df < 8; df++) {
        const int col = h * DEPTH + df * 8 + ec;
        {
            uint32_t hp, lp;
            split_pack2(oacc[df][0] * inv0, oacc[df][1] * inv0, hp, lp);
            const size_t idx = ((size_t)b * S_ + s0) * D_ + col;
            *reinterpret_cast<uint32_t*>(&out_hi[idx]) = hp;
            *reinterpret_cast<uint32_t*>(&out_lo[idx]) = lp;
        }
        {
            uint32_t hp, lp;
            split_pack2(oacc[df][2] * inv1, oacc[df][3] * inv1, hp, lp);
            const size_t idx = ((size_t)b * S_ + s0 + 8) * D_ + col;
            *reinterpret_cast<uint32_t*>(&out_hi[idx]) = hp;
            *reinterpret_cast<uint32_t*>(&out_lo[idx]) = lp;
        }
    }
}

// ---------------------------------------------------------------------------
// Launch
// ---------------------------------------------------------------------------
extern "C" void kernel_launch(void* const* d_in, const int* in_sizes, int n_in,
                              void* d_out, int out_size)
{
    (void)in_sizes; (void)n_in; (void)out_size;
    const float* v_in = (const float*)d_in[0];
    const float* k_in = (const float*)d_in[1];
    const float* q_in = (const float*)d_in[2];
    const float* wq = (const float*)d_in[4];
    const float* bq = (const float*)d_in[5];
    const float* wk = (const float*)d_in[6];
    const float* bk = (const float*)d_in[7];
    const float* wv = (const float*)d_in[8];
    const float* bv = (const float*)d_in[9];
    const float* wo = (const float*)d_in[10];
    const float* bo = (const float*)d_in[11];
    float* out = (float*)d_out;

    __nv_bfloat16 *ih, *il, *wh, *wl, *ah, *al;
    __nv_bfloat16 *qh, *ql, *kh, *kl, *vh, *vl;
    cudaGetSymbolAddress((void**)&ih, g_in_hi);
    cudaGetSymbolAddress((void**)&il, g_in_lo);
    cudaGetSymbolAddress((void**)&wh, g_wt_hi);
    cudaGetSymbolAddress((void**)&wl, g_wt_lo);
    cudaGetSymbolAddress((void**)&ah, g_attn_hi);
    cudaGetSymbolAddress((void**)&al, g_attn_lo);
    cudaGetSymbolAddress((void**)&qh, g_qh);
    cudaGetSymbolAddress((void**)&ql, g_ql);
    cudaGetSymbolAddress((void**)&kh, g_kh);
    cudaGetSymbolAddress((void**)&kl, g_kl);
    cudaGetSymbolAddress((void**)&vh, g_vh);
    cudaGetSymbolAddress((void**)&vl, g_vl);

    static bool attr_set = false;
    if (!attr_set) {
        cudaFuncSetAttribute(attn_mma_kernel,
                             cudaFuncAttributeMaxDynamicSharedMemorySize, ATTN_SMEM);
        cudaFuncSetAttribute(qkv_gemm,
                             cudaFuncAttributeMaxDynamicSharedMemorySize, GEMM_SMEM);
        cudaFuncSetAttribute(out_gemm,
                             cudaFuncAttributeMaxDynamicSharedMemorySize, GEMM_SMEM);
        attr_set = true;
    }

    const size_t ND = (size_t)MTOK * D_;
    const size_t WD = (size_t)D_ * D_;

    // 1) Split inputs (v,k,q) into bf16 hi/lo
    const int n4 = (int)(ND / 4);
    const int cgrid = (n4 + 255) / 256;
    convert_split_kernel<<<cgrid, 256>>>(v_in, ih + 0 * ND, il + 0 * ND, n4);
    convert_split_kernel<<<cgrid, 256>>>(k_in, ih + 1 * ND, il + 1 * ND, n4);
    convert_split_kernel<<<cgrid, 256>>>(q_in, ih + 2 * ND, il + 2 * ND, n4);

    // 2) Transpose + split weights (wq, wk, wv, wo)
    const dim3 tgrid(32, 32), tblock(32, 8);
    transpose_split_kernel<<<tgrid, tblock>>>(wq, wh + 0 * WD, wl + 0 * WD);
    transpose_split_kernel<<<tgrid, tblock>>>(wk, wh + 1 * WD, wl + 1 * WD);
    transpose_split_kernel<<<tgrid, tblock>>>(wv, wh + 2 * WD, wl + 2 * WD);
    transpose_split_kernel<<<tgrid, tblock>>>(wo, wh + 3 * WD, wl + 3 * WD);

    // 3) Fused QKV projections (one launch, grid.z = 3)
    const dim3 qkv_grid(D_ / 128, MTOK / 128, 3);   // (8, 64, 3)
    qkv_gemm<<<qkv_grid, 128, GEMM_SMEM>>>(bq, bk, bv);

    // 4) Causal flash attention (HMMA) -> split-bf16 [B,S,D]
    const dim3 attn_grid(S_ / 64, B_ * H_);   // (32, 64)
    attn_mma_kernel<<<attn_grid, 128, ATTN_SMEM>>>(qh, ql, kh, kl, vh, vl, ah, al);

    // 5) Output projection (fp32 out)
    const dim3 ogrid(D_ / 128, MTOK / 128);   // (8, 64)
    out_gemm<<<ogrid, 128, GEMM_SMEM>>>(bo, out);
}

// round 6
// speedup vs baseline: 7.5490x; 2.3371x over previous
#include <cuda_runtime.h>
#include <cuda_fp16.h>
#include <math.h>
#include <stdint.h>

// Problem constants
#define B_    4
#define S_    2048
#define D_    1024
#define H_    16
#define DEPTH 64
#define MTOK  (B_ * S_)   // 8192 token rows

// ---------------------------------------------------------------------------
// Scratch (device globals; no allocation allowed)
// ---------------------------------------------------------------------------
__device__ __half g_in[3][MTOK * D_];     // fp16 inputs (v,k,q order)
__device__ __half g_wt[4][D_ * D_];       // fp16 transposed weights [N,K]
__device__ __half g_q[MTOK * D_];         // projected, head-split [B,H,S,64]
__device__ __half g_k[MTOK * D_];
__device__ __half g_v[MTOK * D_];
__device__ __half g_attn[MTOK * D_];      // attention output [B,S,D]

// ---------------------------------------------------------------------------
// PTX helpers (sm_103 base target: mma.sync / ldmatrix / cp.async only)
// ---------------------------------------------------------------------------
__device__ __forceinline__ uint32_t smem_u32(const void* p) {
    uint32_t a;
    asm("{ .reg .u64 t; cvta.to.shared.u64 t, %1; cvt.u32.u64 %0, t; }"
        : "=r"(a) : "l"(p));
    return a;
}

#define CP_ASYNC16(dst_u32, src_ptr) \
    asm volatile("cp.async.cg.shared.global [%0], [%1], 16;" \
                 :: "r"(dst_u32), "l"(src_ptr) : "memory")
#define CP_COMMIT() asm volatile("cp.async.commit_group;" ::: "memory")
#define CP_WAIT(n)  asm volatile("cp.async.wait_group %0;" :: "n"(n) : "memory")

#define LDSM_X4(r0, r1, r2, r3, addr) \
    asm volatile("ldmatrix.sync.aligned.m8n8.x4.shared.b16 {%0,%1,%2,%3}, [%4];" \
                 : "=r"(r0), "=r"(r1), "=r"(r2), "=r"(r3) : "r"(addr))

#define LDSM_X4_T(r0, r1, r2, r3, addr) \
    asm volatile("ldmatrix.sync.aligned.m8n8.x4.trans.shared.b16 {%0,%1,%2,%3}, [%4];" \
                 : "=r"(r0), "=r"(r1), "=r"(r2), "=r"(r3) : "r"(addr))

#define MMA_F16(d, a, b) \
    asm volatile("mma.sync.aligned.m16n8k16.row.col.f32.f16.f16.f32 " \
                 "{%0,%1,%2,%3}, {%4,%5,%6,%7}, {%8,%9}, {%0,%1,%2,%3};" \
                 : "+f"((d)[0]), "+f"((d)[1]), "+f"((d)[2]), "+f"((d)[3]) \
                 : "r"((a)[0]), "r"((a)[1]), "r"((a)[2]), "r"((a)[3]), \
                   "r"((b)[0]), "r"((b)[1]))

__device__ __forceinline__ uint32_t pack_h2(float x, float y) {
    __half2 h = __floats2half2_rn(x, y);
    return *reinterpret_cast<uint32_t*>(&h);
}

// ---------------------------------------------------------------------------
// Conversion kernels (fused across tensors via grid.z)
// ---------------------------------------------------------------------------
__global__ void __launch_bounds__(256)
convert_all(const float* __restrict__ v, const float* __restrict__ k,
            const float* __restrict__ q)
{
    const int z = blockIdx.z;
    const float* src = (z == 0) ? v : (z == 1) ? k : q;
    __half* dst = g_in[z];
    const int i = blockIdx.x * blockDim.x + threadIdx.x;   // float4 index
    float4 val = reinterpret_cast<const float4*>(src)[i];
    uint32_t* dp = reinterpret_cast<uint32_t*>(dst);
    dp[2 * i]     = pack_h2(val.x, val.y);
    dp[2 * i + 1] = pack_h2(val.z, val.w);
}

// W[K,N] fp32 -> Wt [N,K] fp16, fused across 4 weights via grid.z
__global__ void __launch_bounds__(256)
transpose_all(const float* __restrict__ wq, const float* __restrict__ wk,
              const float* __restrict__ wv, const float* __restrict__ wo)
{
    __shared__ float t[32][33];
    const int z = blockIdx.z;
    const float* W = (z == 0) ? wq : (z == 1) ? wk : (z == 2) ? wv : wo;
    __half* T = g_wt[z];
    const int tx = threadIdx.x, ty = threadIdx.y;   // (32, 8)
    const int kx = blockIdx.y * 32;
    const int nx = blockIdx.x * 32;
    #pragma unroll
    for (int r = 0; r < 32; r += 8)
        t[ty + r][tx] = W[(size_t)(kx + ty + r) * D_ + nx + tx];
    __syncthreads();
    #pragma unroll
    for (int r = 0; r < 32; r += 8)
        T[(size_t)(nx + ty + r) * D_ + kx + tx] = __float2half_rn(t[tx][ty + r]);
}

// ---------------------------------------------------------------------------
// fp16 HMMA GEMM body. 128x128 CTA tile, 4 warps (2x2), 64x64 warp tiles,
// K-block 32, 3-stage cp.async pipeline.
// MODE 0: C fp32 row-major [M,N]
// MODE 1: C fp16 head-split [B,H,S,DEPTH]
// ---------------------------------------------------------------------------
#define LDT       40                       // smem row stride in fp16 (80B)
#define TILE_B    (128 * LDT * 2)          // 10240 bytes
#define STAGE_B   (2 * TILE_B)             // A + B = 20480
#define GEMM_SMEM (3 * STAGE_B)            // 61440

template <int MODE>
__device__ __forceinline__ void
gemm_body(const __half* __restrict__ A, const __half* __restrict__ Bm,
          const float* __restrict__ bias, float* __restrict__ C,
          __half* __restrict__ Ch, float alpha)
{
    extern __shared__ char smem[];
    const uint32_t sb = smem_u32(smem);

    const int tid  = threadIdx.x;        // 0..127
    const int wid  = tid >> 5;
    const int lane = tid & 31;
    const int wm   = wid & 1;
    const int wn   = wid >> 1;
    const int m0   = blockIdx.y * 128;
    const int n0   = blockIdx.x * 128;

    const __half* srcs[2] = {A, Bm};
    const int rowbase[2] = {m0, n0};

    auto load_stage = [&](int kb, int buf) {
        const uint32_t st = sb + buf * STAGE_B;
        #pragma unroll
        for (int t = 0; t < 2; t++) {
            const __half* s = srcs[t];
            const int rb = rowbase[t];
            #pragma unroll
            for (int r = 0; r < 4; r++) {
                const int idx  = r * 128 + tid;
                const int row  = idx >> 2;
                const int ch   = idx & 3;
                const __half* src = s + (size_t)(rb + row) * D_ + kb * 32 + ch * 8;
                const uint32_t dst = st + t * TILE_B + row * (LDT * 2) + ch * 16;
                CP_ASYNC16(dst, src);
            }
        }
        CP_COMMIT();
    };

    float acc[4][8][4];
    #pragma unroll
    for (int i = 0; i < 4; i++)
        #pragma unroll
        for (int j = 0; j < 8; j++)
            #pragma unroll
            for (int v = 0; v < 4; v++)
                acc[i][j][v] = 0.0f;

    load_stage(0, 0);
    load_stage(1, 1);
    load_stage(2, 2);

    const int a_r = lane & 15;
    const int a_c = (lane >> 4) << 3;
    const int b_r = (lane & 7) + ((lane >> 4) << 3);
    const int b_c = ((lane >> 3) & 1) << 3;

    const int NITER = D_ / 32;    // 32
    for (int kb = 0; kb < NITER; kb++) {
        if (kb <= NITER - 3)      { CP_WAIT(2); }
        else if (kb == NITER - 2) { CP_WAIT(1); }
        else                      { CP_WAIT(0); }
        __syncthreads();

        const int buf = kb - (kb / 3) * 3;
        const uint32_t st = sb + buf * STAGE_B;
        const uint32_t tA = st;
        const uint32_t tB = st + TILE_B;

        #pragma unroll
        for (int ks = 0; ks < 32; ks += 16) {
            uint32_t ah[4][4];
            #pragma unroll
            for (int mf = 0; mf < 4; mf++) {
                const int row = wm * 64 + mf * 16 + a_r;
                const uint32_t off = row * (LDT * 2) + (ks + a_c) * 2;
                LDSM_X4(ah[mf][0], ah[mf][1], ah[mf][2], ah[mf][3], tA + off);
            }
            uint32_t bh[8][2];
            #pragma unroll
            for (int gp = 0; gp < 4; gp++) {
                const int row = wn * 64 + gp * 16 + b_r;
                const uint32_t off = row * (LDT * 2) + (ks + b_c) * 2;
                LDSM_X4(bh[2 * gp][0], bh[2 * gp][1], bh[2 * gp + 1][0], bh[2 * gp + 1][1],
                        tB + off);
            }
            #pragma unroll
            for (int mf = 0; mf < 4; mf++)
                #pragma unroll
                for (int nf = 0; nf < 8; nf++)
                    MMA_F16(acc[mf][nf], ah[mf], bh[nf]);
        }
        __syncthreads();
        if (kb + 3 < NITER) load_stage(kb + 3, buf);
    }

    const int er = lane >> 2;
    const int ec = (lane & 3) * 2;
    #pragma unroll
    for (int mf = 0; mf < 4; mf++) {
        #pragma unroll
        for (int nf = 0; nf < 8; nf++) {
            const int n  = n0 + wn * 64 + nf * 8 + ec;
            const float b0 = bias[n], b1 = bias[n + 1];
            #pragma unroll
            for (int half = 0; half < 2; half++) {
                const int m = m0 + wm * 64 + mf * 16 + er + half * 8;
                const float vx = (acc[mf][nf][half * 2 + 0] + b0) * alpha;
                const float vy = (acc[mf][nf][half * 2 + 1] + b1) * alpha;
                if (MODE == 0) {
                    float2 v; v.x = vx; v.y = vy;
                    *reinterpret_cast<float2*>(&C[(size_t)m * D_ + n]) = v;
                } else {
                    const int b  = m >> 11;
                    const int s  = m & 2047;
                    const int h  = n >> 6;
                    const int dd = n & 63;
                    const size_t idx = (((size_t)(b * H_ + h)) * S_ + s) * DEPTH + dd;
                    *reinterpret_cast<uint32_t*>(&Ch[idx]) = pack_h2(vx, vy);
                }
            }
        }
    }
}

// Fused QKV projection: grid.z selects {q,k,v}. Q pre-scaled by 1/8.
__global__ void __launch_bounds__(128)
qkv_gemm(const float* __restrict__ bq, const float* __restrict__ bk,
         const float* __restrict__ bv)
{
    const int z = blockIdx.z;
    if (z == 0) {
        gemm_body<1>(g_in[2], g_wt[0], bq, nullptr, g_q, 0.125f);
    } else if (z == 1) {
        gemm_body<1>(g_in[1], g_wt[1], bk, nullptr, g_k, 1.0f);
    } else {
        gemm_body<1>(g_in[0], g_wt[2], bv, nullptr, g_v, 1.0f);
    }
}

__global__ void __launch_bounds__(128)
out_gemm(const float* __restrict__ bo, float* __restrict__ C)
{
    gemm_body<0>(g_attn, g_wt[3], bo, C, nullptr, 1.0f);
}

// ---------------------------------------------------------------------------
// Flash attention via fp16 HMMA.
// Grid: (S/64, B*H). Block: 128 threads (4 warps; warp w owns q-rows w*16..+15).
// Q pre-scaled by 1/8 in projection. Causal: kt in [0, qt].
// ---------------------------------------------------------------------------
#define ALD       72                       // smem stride in fp16 (144B)
#define ATILE_B   (64 * ALD * 2)           // 9216 bytes per 64x64 tile
#define ASTAGE_B  (2 * ATILE_B)            // K, V = 18432
#define AQ_B      ATILE_B                  // Q = 9216
#define ATTN_SMEM (AQ_B + 2 * ASTAGE_B)    // 46080

__global__ void __launch_bounds__(128)
attn_mma_kernel(__half* __restrict__ out)
{
    extern __shared__ char smem[];
    const uint32_t sb     = smem_u32(smem);
    const uint32_t sQ     = sb;
    const uint32_t sStage = sb + AQ_B;

    const int tid  = threadIdx.x;
    const int wid  = tid >> 5;
    const int lane = tid & 31;
    const int qt   = blockIdx.x;
    const int bh   = blockIdx.y;
    const int q0   = qt * 64;

    const size_t headbase = (size_t)bh * S_ * DEPTH;

    // ---- Load Q tile ----
    {
        const __half* s = g_q + headbase + (size_t)q0 * DEPTH;
        #pragma unroll
        for (int i = 0; i < 4; i++) {
            const int idx = i * 128 + tid;
            const int row = idx >> 3, ch = idx & 7;
            CP_ASYNC16(sQ + row * (ALD * 2) + ch * 16, s + row * DEPTH + ch * 8);
        }
    }

    auto load_kv = [&](int kt, int buf) {
        const uint32_t st = sStage + buf * ASTAGE_B;
        const size_t base = headbase + (size_t)kt * 64 * DEPTH;
        const __half* kvsrc[2] = {g_k + base, g_v + base};
        #pragma unroll
        for (int t = 0; t < 2; t++) {
            const __half* s = kvsrc[t];
            #pragma unroll
            for (int i = 0; i < 4; i++) {
                const int idx = i * 128 + tid;
                const int row = idx >> 3, ch = idx & 7;
                CP_ASYNC16(st + t * ATILE_B + row * (ALD * 2) + ch * 16,
                           s + row * DEPTH + ch * 8);
            }
        }
    };

    load_kv(0, 0);
    CP_COMMIT();
    CP_WAIT(0);
    __syncthreads();

    // ---- Q fragments to registers ----
    const int a_r = lane & 15;
    const int a_c = (lane >> 4) << 3;
    uint32_t aq[4][4];
    {
        const int row = wid * 16 + a_r;
        #pragma unroll
        for (int t = 0; t < 4; t++) {
            const uint32_t off = row * (ALD * 2) + (t * 16 + a_c) * 2;
            LDSM_X4(aq[t][0], aq[t][1], aq[t][2], aq[t][3], sQ + off);
        }
    }

    const int b_r = (lane & 7) + ((lane >> 4) << 3);
    const int b_c = ((lane >> 3) & 1) << 3;
    const int v_r = (lane & 7) + (((lane >> 3) & 1) << 3);
    const int v_c = (lane >> 4) << 3;
    const int er  = lane >> 2;
    const int ec  = (lane & 3) * 2;

    float oacc[8][4];
    #pragma unroll
    for (int j = 0; j < 8; j++)
        #pragma unroll
        for (int v = 0; v < 4; v++) oacc[j][v] = 0.0f;
    float m0 = -1e30f, m1 = -1e30f, l0 = 0.0f, l1 = 0.0f;

    for (int kt = 0; kt <= qt; kt++) {
        const int buf = kt & 1;
        if (kt < qt) { load_kv(kt + 1, buf ^ 1); CP_COMMIT(); CP_WAIT(1); }
        else         { CP_WAIT(0); }
        __syncthreads();

        const uint32_t st = sStage + buf * ASTAGE_B;
        const uint32_t tK = st;
        const uint32_t tV = st + ATILE_B;

        // ---- Scores ----
        float sacc[8][4];
        #pragma unroll
        for (int j = 0; j < 8; j++)
            #pragma unroll
            for (int v = 0; v < 4; v++) sacc[j][v] = 0.0f;

        #pragma unroll
        for (int t = 0; t < 4; t++) {
            uint32_t kb[8][2];
            #pragma unroll
            for (int g = 0; g < 4; g++) {
                const int row = g * 16 + b_r;
                const uint32_t off = row * (ALD * 2) + (t * 16 + b_c) * 2;
                LDSM_X4(kb[2 * g][0], kb[2 * g][1], kb[2 * g + 1][0], kb[2 * g + 1][1],
                        tK + off);
            }
            #pragma unroll
            for (int nf = 0; nf < 8; nf++)
                MMA_F16(sacc[nf], aq[t], kb[nf]);
        }

        // ---- Causal mask on diagonal tile ----
        if (kt == qt) {
            const int r0_ = wid * 16 + er;
            const int r1_ = r0_ + 8;
            #pragma unroll
            for (int nf = 0; nf < 8; nf++) {
                const int c0_ = nf * 8 + ec;
                if (c0_ > r0_)     sacc[nf][0] = -1e30f;
                if (c0_ + 1 > r0_) sacc[nf][1] = -1e30f;
                if (c0_ > r1_)     sacc[nf][2] = -1e30f;
                if (c0_ + 1 > r1_) sacc[nf][3] = -1e30f;
            }
        }

        // ---- Online softmax ----
        float mn0 = -1e30f, mn1 = -1e30f;
        #pragma unroll
        for (int nf = 0; nf < 8; nf++) {
            mn0 = fmaxf(mn0, fmaxf(sacc[nf][0], sacc[nf][1]));
            mn1 = fmaxf(mn1, fmaxf(sacc[nf][2], sacc[nf][3]));
        }
        mn0 = fmaxf(mn0, __shfl_xor_sync(0xffffffffu, mn0, 1));
        mn0 = fmaxf(mn0, __shfl_xor_sync(0xffffffffu, mn0, 2));
        mn1 = fmaxf(mn1, __shfl_xor_sync(0xffffffffu, mn1, 1));
        mn1 = fmaxf(mn1, __shfl_xor_sync(0xffffffffu, mn1, 2));

        const float nm0 = fmaxf(m0, mn0);
        const float nm1 = fmaxf(m1, mn1);
        const float corr0 = __expf(m0 - nm0);
        const float corr1 = __expf(m1 - nm1);
        m0 = nm0; m1 = nm1;

        float rs0 = 0.0f, rs1 = 0.0f;
        #pragma unroll
        for (int nf = 0; nf < 8; nf++) {
            sacc[nf][0] = __expf(sacc[nf][0] - nm0);
            sacc[nf][1] = __expf(sacc[nf][1] - nm0);
            sacc[nf][2] = __expf(sacc[nf][2] - nm1);
            sacc[nf][3] = __expf(sacc[nf][3] - nm1);
            rs0 += sacc[nf][0] + sacc[nf][1];
            rs1 += sacc[nf][2] + sacc[nf][3];
        }
        rs0 += __shfl_xor_sync(0xffffffffu, rs0, 1);
        rs0 += __shfl_xor_sync(0xffffffffu, rs0, 2);
        rs1 += __shfl_xor_sync(0xffffffffu, rs1, 1);
        rs1 += __shfl_xor_sync(0xffffffffu, rs1, 2);
        l0 = l0 * corr0 + rs0;
        l1 = l1 * corr1 + rs1;

        #pragma unroll
        for (int j = 0; j < 8; j++) {
            oacc[j][0] *= corr0; oacc[j][1] *= corr0;
            oacc[j][2] *= corr1; oacc[j][3] *= corr1;
        }

        // ---- P -> fp16 A fragments ----
        uint32_t ph[4][4];
        #pragma unroll
        for (int t = 0; t < 4; t++) {
            ph[t][0] = pack_h2(sacc[2 * t][0],     sacc[2 * t][1]);
            ph[t][1] = pack_h2(sacc[2 * t][2],     sacc[2 * t][3]);
            ph[t][2] = pack_h2(sacc[2 * t + 1][0], sacc[2 * t + 1][1]);
            ph[t][3] = pack_h2(sacc[2 * t + 1][2], sacc[2 * t + 1][3]);
        }

        // ---- O += P @ V ----
        #pragma unroll
        for (int t = 0; t < 4; t++) {
            uint32_t vb[8][2];
            #pragma unroll
            for (int g = 0; g < 4; g++) {
                const int row = t * 16 + v_r;
                const uint32_t off = row * (ALD * 2) + (g * 16 + v_c) * 2;
                LDSM_X4_T(vb[2 * g][0], vb[2 * g][1], vb[2 * g + 1][0], vb[2 * g + 1][1],
                          tV + off);
            }
            #pragma unroll
            for (int df = 0; df < 8; df++)
                MMA_F16(oacc[df], ph[t], vb[df]);
        }
        __syncthreads();
    }

    // ---- Normalize and write out [B,S,D] ----
    const int b = bh >> 4;
    const int h = bh & 15;
    const float inv0 = 1.0f / l0;
    const float inv1 = 1.0f / l1;
    const int s0 = q0 + wid * 16 + er;
    #pragma unroll
    for (int df = 0; df < 8; df++) {
        const int col = h * DEPTH + df * 8 + ec;
        *reinterpret_cast<uint32_t*>(&out[((size_t)b * S_ + s0) * D_ + col]) =
            pack_h2(oacc[df][0] * inv0, oacc[df][1] * inv0);
        *reinterpret_cast<uint32_t*>(&out[((size_t)b * S_ + s0 + 8) * D_ + col]) =
            pack_h2(oacc[df][2] * inv1, oacc[df][3] * inv1);
    }
}

// ---------------------------------------------------------------------------
// Launch
// ---------------------------------------------------------------------------
extern "C" void kernel_launch(void* const* d_in, const int* in_sizes, int n_in,
                              void* d_out, int out_size)
{
    (void)in_sizes; (void)n_in; (void)out_size;
    const float* v_in = (const float*)d_in[0];
    const float* k_in = (const float*)d_in[1];
    const float* q_in = (const float*)d_in[2];
    const float* wq = (const float*)d_in[4];
    const float* bq = (const float*)d_in[5];
    const float* wk = (const float*)d_in[6];
    const float* bk = (const float*)d_in[7];
    const float* wv = (const float*)d_in[8];
    const float* bv = (const float*)d_in[9];
    const float* wo = (const float*)d_in[10];
    const float* bo = (const float*)d_in[11];
    float* out = (float*)d_out;

    __half* attn_ptr;
    cudaGetSymbolAddress((void**)&attn_ptr, g_attn);

    static bool attr_set = false;
    if (!attr_set) {
        cudaFuncSetAttribute(attn_mma_kernel,
                             cudaFuncAttributeMaxDynamicSharedMemorySize, ATTN_SMEM);
        cudaFuncSetAttribute(qkv_gemm,
                             cudaFuncAttributeMaxDynamicSharedMemorySize, GEMM_SMEM);
        cudaFuncSetAttribute(out_gemm,
                             cudaFuncAttributeMaxDynamicSharedMemorySize, GEMM_SMEM);
        attr_set = true;
    }

    // 1) Convert inputs to fp16 (one launch, z = {v,k,q})
    const int n4 = (int)((size_t)MTOK * D_ / 4);
    const dim3 cgrid(n4 / 256, 1, 3);
    convert_all<<<cgrid, 256>>>(v_in, k_in, q_in);

    // 2) Transpose weights to fp16 [N,K] (one launch, z = {wq,wk,wv,wo})
    const dim3 tgrid(32, 32, 4), tblock(32, 8);
    transpose_all<<<tgrid, tblock>>>(wq, wk, wv, wo);

    // 3) Fused QKV projections; Q pre-scaled by 1/8
    const dim3 qkv_grid(D_ / 128, MTOK / 128, 3);   // (8, 64, 3)
    qkv_gemm<<<qkv_grid, 128, GEMM_SMEM>>>(bq, bk, bv);

    // 4) Causal flash attention (fp16 HMMA) -> fp16 [B,S,D]
    const dim3 attn_grid(S_ / 64, B_ * H_);   // (32, 64)
    attn_mma_kernel<<<attn_grid, 128, ATTN_SMEM>>>(attn_ptr);

    // 5) Output projection (fp32 out)
    const dim3 ogrid(D_ / 128, MTOK / 128);   // (8, 64)
    out_gemm<<<ogrid, 128, GEMM_SMEM>>>(bo, out);
}